// round 4
// baseline (speedup 1.0000x reference)
#include <cuda_runtime.h>
#include <cuda_bf16.h>
#include <cstdint>

// Problem constants
#define B_   256
#define NV_  196
#define LT_  32
#define CI_  768
#define CT_  512
#define NROWS (B_*NV_)      // 50176
#define KVROWS (B_*LT_)     // 8192

// -------------------- scratch (device globals; no allocation) --------------------
__device__ __nv_bfloat16 g_vis_hi [(size_t)NROWS * CI_];
__device__ __nv_bfloat16 g_vis_lo [(size_t)NROWS * CI_];
__device__ __nv_bfloat16 g_text_hi[(size_t)KVROWS * CT_];
__device__ __nv_bfloat16 g_text_lo[(size_t)KVROWS * CT_];
__device__ __nv_bfloat16 g_wqT_hi [(size_t)CI_ * CI_];
__device__ __nv_bfloat16 g_wqT_lo [(size_t)CI_ * CI_];
__device__ __nv_bfloat16 g_wkT_hi [(size_t)CI_ * CT_];
__device__ __nv_bfloat16 g_wkT_lo [(size_t)CI_ * CT_];
__device__ __nv_bfloat16 g_wvT_hi [(size_t)CI_ * CT_];
__device__ __nv_bfloat16 g_wvT_lo [(size_t)CI_ * CT_];
__device__ __nv_bfloat16 g_w1T_hi [(size_t)CI_ * CI_];
__device__ __nv_bfloat16 g_w1T_lo [(size_t)CI_ * CI_];
__device__ __nv_bfloat16 g_fused_hi[(size_t)NROWS * CI_];
__device__ __nv_bfloat16 g_fused_lo[(size_t)NROWS * CI_];
__device__ float g_q[(size_t)NROWS * CI_];
__device__ float g_k[(size_t)KVROWS * CI_];
__device__ float g_v[(size_t)KVROWS * CI_];
__device__ float g_h[(size_t)NROWS * CI_];

// -------------------- small helpers --------------------
__device__ __forceinline__ float qgelu(float x) {
    return x / (1.0f + __expf(-1.702f * x));
}
__device__ __forceinline__ void split_bf(float x, __nv_bfloat16& h, __nv_bfloat16& l) {
    h = __float2bfloat16(x);
    l = __float2bfloat16(x - __bfloat162float(h));
}
__device__ __forceinline__ uint32_t pack_bf2(__nv_bfloat16 a, __nv_bfloat16 b) {
    uint32_t la = (uint32_t)__bfloat16_as_ushort(a);
    uint32_t lb = (uint32_t)__bfloat16_as_ushort(b);
    return la | (lb << 16);
}
__device__ __forceinline__ uint32_t smem_u32(const void* p) {
    uint32_t a;
    asm("{ .reg .u64 t; cvta.to.shared.u64 t, %1; cvt.u32.u64 %0, t; }" : "=r"(a) : "l"(p));
    return a;
}

// -------------------- mma / ldmatrix / cp.async primitives (base sm_103) --------
__device__ __forceinline__ void ldsm_x4(uint32_t* r, uint32_t addr) {
    asm volatile("ldmatrix.sync.aligned.m8n8.x4.shared.b16 {%0,%1,%2,%3}, [%4];"
                 : "=r"(r[0]), "=r"(r[1]), "=r"(r[2]), "=r"(r[3]) : "r"(addr));
}
__device__ __forceinline__ void mma_bf16(float* d, const uint32_t* a, const uint32_t* b) {
    asm volatile(
        "mma.sync.aligned.m16n8k16.row.col.f32.bf16.bf16.f32 "
        "{%0,%1,%2,%3}, {%4,%5,%6,%7}, {%8,%9}, {%0,%1,%2,%3};"
        : "+f"(d[0]), "+f"(d[1]), "+f"(d[2]), "+f"(d[3])
        : "r"(a[0]), "r"(a[1]), "r"(a[2]), "r"(a[3]), "r"(b[0]), "r"(b[1]));
}
__device__ __forceinline__ void cp_async16(uint32_t dst, const void* src) {
    asm volatile("cp.async.ca.shared.global [%0], [%1], 16;" :: "r"(dst), "l"(src));
}
__device__ __forceinline__ void cp_commit() {
    asm volatile("cp.async.commit_group;");
}
__device__ __forceinline__ void cp_wait1() {
    asm volatile("cp.async.wait_group 1;");
}

// -------------------- bf16x3 tensor-core GEMM --------------------
// C[M,768] = (Ahi+Alo) @ (Bhi+Blo)^T + bias (opt gelu).
// Tile 128x128x32, 256 threads, 3-stage cp.async pipeline.
#define SST 40                      // smem row stride in halfwords (80 bytes)
#define TILE_B (128 * SST * 2)      // 10240 bytes per tile
#define STAGE_B (4 * TILE_B)        // Ah, Al, Bh, Bl
#define GEMM_SMEM (3 * STAGE_B)     // 122880 bytes

__device__ __forceinline__ void issue_tile(uint32_t dst, const __nv_bfloat16* src,
                                           int ld, int tid) {
#pragma unroll
    for (int it = 0; it < 2; it++) {
        int id = tid + it * 256;
        int r = id >> 2, c = id & 3;
        cp_async16(dst + r * (SST * 2) + c * 16, src + (size_t)r * ld + c * 8);
    }
}

template<int KDIM, int DO_GELU>
__global__ __launch_bounds__(256, 1)
void gemm_mma(const __nv_bfloat16* __restrict__ Ahi, const __nv_bfloat16* __restrict__ Alo,
              const __nv_bfloat16* __restrict__ Bhi, const __nv_bfloat16* __restrict__ Blo,
              const float* __restrict__ bias, float* __restrict__ C) {
    extern __shared__ char smem[];
    const int tid = threadIdx.x;
    const int lane = tid & 31;
    const int wid = tid >> 5;
    const int wm = wid & 3;
    const int wn = wid >> 2;
    const int n0 = blockIdx.x * 128;
    const int m0 = blockIdx.y * 128;

    const uint32_t sbase = smem_u32(smem);

    const __nv_bfloat16* Ah = Ahi + (size_t)m0 * KDIM;
    const __nv_bfloat16* Al = Alo + (size_t)m0 * KDIM;
    const __nv_bfloat16* Bh = Bhi + (size_t)n0 * KDIM;
    const __nv_bfloat16* Bl = Blo + (size_t)n0 * KDIM;

    constexpr int NC = KDIM / 32;

    float acc[2][8][4];
#pragma unroll
    for (int i = 0; i < 2; i++)
#pragma unroll
        for (int j = 0; j < 8; j++)
#pragma unroll
            for (int k = 0; k < 4; k++) acc[i][j][k] = 0.f;

#pragma unroll
    for (int p = 0; p < 2; p++) {
        uint32_t st = sbase + p * STAGE_B;
        issue_tile(st,              Ah + p * 32, KDIM, tid);
        issue_tile(st + TILE_B,     Al + p * 32, KDIM, tid);
        issue_tile(st + 2 * TILE_B, Bh + p * 32, KDIM, tid);
        issue_tile(st + 3 * TILE_B, Bl + p * 32, KDIM, tid);
        cp_commit();
    }

    const int a_row = wm * 32 + (lane & 15);
    const int a_colb = ((lane >> 4) << 3) * 2;
    const int b_row = wn * 64 + (lane & 7) + ((lane >> 4) << 3);
    const int b_colb = (((lane >> 3) & 1) << 3) * 2;

    for (int c = 0; c < NC; c++) {
        cp_wait1();
        __syncthreads();
        if (c + 2 < NC) {
            uint32_t st = sbase + ((c + 2) % 3) * STAGE_B;
            int k0 = (c + 2) * 32;
            issue_tile(st,              Ah + k0, KDIM, tid);
            issue_tile(st + TILE_B,     Al + k0, KDIM, tid);
            issue_tile(st + 2 * TILE_B, Bh + k0, KDIM, tid);
            issue_tile(st + 3 * TILE_B, Bl + k0, KDIM, tid);
        }
        cp_commit();

        uint32_t st = sbase + (c % 3) * STAGE_B;
#pragma unroll
        for (int ks = 0; ks < 2; ks++) {
            const int kb = ks * 32;
            uint32_t Ahf[2][4], Alf[2][4];
#pragma unroll
            for (int mi = 0; mi < 2; mi++) {
                uint32_t arow = (a_row + mi * 16) * (SST * 2) + kb + a_colb;
                ldsm_x4(Ahf[mi], st + arow);
                ldsm_x4(Alf[mi], st + TILE_B + arow);
            }
            uint32_t Bhf[4][4], Blf[4][4];
#pragma unroll
            for (int ni2 = 0; ni2 < 4; ni2++) {
                uint32_t brow = (b_row + ni2 * 16) * (SST * 2) + kb + b_colb;
                ldsm_x4(Bhf[ni2], st + 2 * TILE_B + brow);
                ldsm_x4(Blf[ni2], st + 3 * TILE_B + brow);
            }
#pragma unroll
            for (int mi = 0; mi < 2; mi++)
#pragma unroll
                for (int ni = 0; ni < 8; ni++) {
                    const int ni2 = ni >> 1, od = (ni & 1) * 2;
                    mma_bf16(acc[mi][ni], Ahf[mi], &Bhf[ni2][od]);
                    mma_bf16(acc[mi][ni], Ahf[mi], &Blf[ni2][od]);
                    mma_bf16(acc[mi][ni], Alf[mi], &Bhf[ni2][od]);
                }
        }
        __syncthreads();
    }

#pragma unroll
    for (int mi = 0; mi < 2; mi++) {
        int row0 = m0 + wm * 32 + mi * 16 + (lane >> 2);
#pragma unroll
        for (int ni = 0; ni < 8; ni++) {
            int col = n0 + wn * 64 + ni * 8 + (lane & 3) * 2;
            float b0 = bias[col], b1 = bias[col + 1];
            float v0 = acc[mi][ni][0] + b0;
            float v1 = acc[mi][ni][1] + b1;
            float v2 = acc[mi][ni][2] + b0;
            float v3 = acc[mi][ni][3] + b1;
            if (DO_GELU) {
                v0 = qgelu(v0); v1 = qgelu(v1); v2 = qgelu(v2); v3 = qgelu(v3);
            }
            *(float2*)(C + (size_t)row0 * 768 + col)       = make_float2(v0, v1);
            *(float2*)(C + (size_t)(row0 + 8) * 768 + col) = make_float2(v2, v3);
        }
    }
}

// -------------------- elementwise fp32 -> bf16 hi/lo split --------------------
__global__ __launch_bounds__(256)
void split_kernel(const float* __restrict__ x, __nv_bfloat16* __restrict__ hi,
                  __nv_bfloat16* __restrict__ lo, int n4) {
    int i = blockIdx.x * blockDim.x + threadIdx.x;
    if (i >= n4) return;
    float4 v = ((const float4*)x)[i];
    __nv_bfloat16 h0, h1, h2, h3, l0, l1, l2, l3;
    split_bf(v.x, h0, l0);
    split_bf(v.y, h1, l1);
    split_bf(v.z, h2, l2);
    split_bf(v.w, h3, l3);
    ((uint2*)hi)[i] = make_uint2(pack_bf2(h0, h1), pack_bf2(h2, h3));
    ((uint2*)lo)[i] = make_uint2(pack_bf2(l0, l1), pack_bf2(l2, l3));
}

// -------------------- weight transpose + split: W[K,N] -> T[N,K] hi/lo --------
__global__ __launch_bounds__(256)
void transpose_split(const float* __restrict__ W, __nv_bfloat16* __restrict__ Thi,
                     __nv_bfloat16* __restrict__ Tlo, int K, int N) {
    __shared__ float t[32][33];
    int n0 = blockIdx.x * 32, k0 = blockIdx.y * 32;
    int tx = threadIdx.x & 31, ty = threadIdx.x >> 5;
#pragma unroll
    for (int s = 0; s < 4; s++)
        t[ty + 8 * s][tx] = W[(size_t)(k0 + ty + 8 * s) * N + n0 + tx];
    __syncthreads();
#pragma unroll
    for (int s = 0; s < 4; s++) {
        int n = n0 + ty + 8 * s;
        int k = k0 + tx;
        float v = t[tx][ty + 8 * s];
        __nv_bfloat16 h, l;
        split_bf(v, h, l);
        Thi[(size_t)n * K + k] = h;
        Tlo[(size_t)n * K + k] = l;
    }
}

// -------------------- attention (register-lean); emits fused hi/lo bf16 --------
// One thread per q-row. q streamed per-d4-chunk (L1-resident re-reads) so only
// s[32] persists across passes -> <=64 regs -> 4 CTAs/SM.
__global__ __launch_bounds__(256, 4)
void attn_kernel(const float* __restrict__ q_s, const float* __restrict__ k_s,
                 const float* __restrict__ v_s, const float* __restrict__ vis,
                 __nv_bfloat16* __restrict__ f_hi, __nv_bfloat16* __restrict__ f_lo) {
    int h = blockIdx.x;
    int b = blockIdx.y;
    __shared__ float4 ksm[32][16];
    __shared__ float4 vsm[32][16];
    int tid = threadIdx.x;

    const float* kbase = k_s + (size_t)b * 32 * 768 + h * 64;
    const float* vbase = v_s + (size_t)b * 32 * 768 + h * 64;
    for (int i = tid; i < 512; i += 256) {
        int l = i >> 4, d4 = i & 15;
        ksm[l][d4] = *(const float4*)(kbase + (size_t)l * 768 + d4 * 4);
        vsm[l][d4] = *(const float4*)(vbase + (size_t)l * 768 + d4 * 4);
    }
    __syncthreads();

    int n = tid;
    if (n >= 196) return;
    size_t rowoff = (size_t)(b * 196 + n) * 768 + h * 64;
    const float4* qrow = (const float4*)(q_s + rowoff);

    float s[32];
#pragma unroll
    for (int l = 0; l < 32; l++) s[l] = 0.f;

    // pass 1: scores (q streamed, not held)
    for (int d4 = 0; d4 < 16; d4++) {
        float4 q4 = qrow[d4];
#pragma unroll
        for (int l = 0; l < 32; l++) {
            float4 kk = ksm[l][d4];
            s[l] += q4.x * kk.x + q4.y * kk.y + q4.z * kk.z + q4.w * kk.w;
        }
    }
    float m = s[0] * 0.125f;
#pragma unroll
    for (int l = 1; l < 32; l++) m = fmaxf(m, s[l] * 0.125f);
    float sum = 0.f;
#pragma unroll
    for (int l = 0; l < 32; l++) {
        s[l] = __expf(s[l] * 0.125f - m);
        sum += s[l];
    }
    float inv = 1.0f / sum;
#pragma unroll
    for (int l = 0; l < 32; l++) s[l] *= inv;

    // pass 2: context + residual + split-store
    const float4* visrow = (const float4*)(vis + rowoff);
    uint2* hrow = (uint2*)(f_hi + rowoff);
    uint2* lrow = (uint2*)(f_lo + rowoff);
    for (int d4 = 0; d4 < 16; d4++) {
        float ax = 0.f, ay = 0.f, az = 0.f, aw = 0.f;
#pragma unroll
        for (int l = 0; l < 32; l++) {
            float4 vv = vsm[l][d4];
            float p = s[l];
            ax += p * vv.x;
            ay += p * vv.y;
            az += p * vv.z;
            aw += p * vv.w;
        }
        float4 r = visrow[d4];
        float o0 = ax + r.x;
        float o1 = ay + r.y;
        float o2 = az + r.z;
        float o3 = aw + r.w;
        __nv_bfloat16 h0, h1, h2, h3, l0, l1, l2, l3;
        split_bf(o0, h0, l0);
        split_bf(o1, h1, l1);
        split_bf(o2, h2, l2);
        split_bf(o3, h3, l3);
        hrow[d4] = make_uint2(pack_bf2(h0, h1), pack_bf2(h2, h3));
        lrow[d4] = make_uint2(pack_bf2(l0, l1), pack_bf2(l2, l3));
    }
}

// -------------------- thin head: logits = h @ W2[768,2] + b2 --------------------
__global__ __launch_bounds__(256)
void logits_kernel(const float* __restrict__ h_s, const float* __restrict__ W2,
                   const float* __restrict__ b2, float* __restrict__ out) {
    int gwarp = (blockIdx.x * blockDim.x + threadIdx.x) >> 5;
    int lane = threadIdx.x & 31;
    if (gwarp >= NROWS) return;
    const float* row = h_s + (size_t)gwarp * 768;
    const float2* w2 = (const float2*)W2;
    float a0 = 0.f, a1 = 0.f;
#pragma unroll
    for (int i = 0; i < 24; i++) {
        int idx = lane + 32 * i;
        float x = row[idx];
        float2 w = w2[idx];
        a0 += x * w.x;
        a1 += x * w.y;
    }
#pragma unroll
    for (int off = 16; off > 0; off >>= 1) {
        a0 += __shfl_xor_sync(0xffffffffu, a0, off);
        a1 += __shfl_xor_sync(0xffffffffu, a1, off);
    }
    if (lane == 0) {
        out[(size_t)gwarp * 2]     = a0 + b2[0];
        out[(size_t)gwarp * 2 + 1] = a1 + b2[1];
    }
}

// rel_BN = attn.mean(-1).mean(1) == 1/Lt exactly (softmax rows sum to 1)
__global__ void fill_rel(float* __restrict__ p) {
    int i = blockIdx.x * blockDim.x + threadIdx.x;
    if (i < NROWS) p[i] = 1.0f / 32.0f;
}

// -------------------- host launch --------------------
extern "C" void kernel_launch(void* const* d_in, const int* in_sizes, int n_in,
                              void* d_out, int out_size) {
    const float* vis  = (const float*)d_in[0];
    const float* text = (const float*)d_in[1];
    const float* Wq   = (const float*)d_in[2];
    const float* bq   = (const float*)d_in[3];
    const float* Wk   = (const float*)d_in[4];
    const float* bk   = (const float*)d_in[5];
    const float* Wv   = (const float*)d_in[6];
    const float* bv   = (const float*)d_in[7];
    const float* W1   = (const float*)d_in[8];
    const float* b1   = (const float*)d_in[9];
    const float* W2   = (const float*)d_in[10];
    const float* b2   = (const float*)d_in[11];
    float* out = (float*)d_out;

    __nv_bfloat16 *vh, *vl, *th, *tl, *wqh, *wql, *wkh, *wkl, *wvh, *wvl, *w1h, *w1l, *fh, *fl;
    float *qs, *ks, *vsc, *hs;
    cudaGetSymbolAddress((void**)&vh,  g_vis_hi);
    cudaGetSymbolAddress((void**)&vl,  g_vis_lo);
    cudaGetSymbolAddress((void**)&th,  g_text_hi);
    cudaGetSymbolAddress((void**)&tl,  g_text_lo);
    cudaGetSymbolAddress((void**)&wqh, g_wqT_hi);
    cudaGetSymbolAddress((void**)&wql, g_wqT_lo);
    cudaGetSymbolAddress((void**)&wkh, g_wkT_hi);
    cudaGetSymbolAddress((void**)&wkl, g_wkT_lo);
    cudaGetSymbolAddress((void**)&wvh, g_wvT_hi);
    cudaGetSymbolAddress((void**)&wvl, g_wvT_lo);
    cudaGetSymbolAddress((void**)&w1h, g_w1T_hi);
    cudaGetSymbolAddress((void**)&w1l, g_w1T_lo);
    cudaGetSymbolAddress((void**)&fh,  g_fused_hi);
    cudaGetSymbolAddress((void**)&fl,  g_fused_lo);
    cudaGetSymbolAddress((void**)&qs,  g_q);
    cudaGetSymbolAddress((void**)&ks,  g_k);
    cudaGetSymbolAddress((void**)&vsc, g_v);
    cudaGetSymbolAddress((void**)&hs,  g_h);

    cudaFuncSetAttribute(gemm_mma<768, 0>, cudaFuncAttributeMaxDynamicSharedMemorySize, GEMM_SMEM);
    cudaFuncSetAttribute(gemm_mma<512, 0>, cudaFuncAttributeMaxDynamicSharedMemorySize, GEMM_SMEM);
    cudaFuncSetAttribute(gemm_mma<768, 1>, cudaFuncAttributeMaxDynamicSharedMemorySize, GEMM_SMEM);

    // Launch order arranged so ncu (-s 5 -c 1) captures gemm_mma<768,0> (launch #6).
    // 1: split vis
    {
        int n4 = NROWS * CI_ / 4;
        split_kernel<<<(n4 + 255) / 256, 256>>>(vis, vh, vl, n4);
    }
    // 2: split text
    {
        int n4 = KVROWS * CT_ / 4;
        split_kernel<<<(n4 + 255) / 256, 256>>>(text, th, tl, n4);
    }
    // 3-5: weight transposes needed before gemm Q
    transpose_split<<<dim3(CI_ / 32, CI_ / 32), 256>>>(Wq, wqh, wql, CI_, CI_);
    transpose_split<<<dim3(CI_ / 32, CI_ / 32), 256>>>(W1, w1h, w1l, CI_, CI_);
    transpose_split<<<dim3(CI_ / 32, CT_ / 32), 256>>>(Wk, wkh, wkl, CT_, CI_);
    // 6: Q projection  <-- profiled launch
    gemm_mma<768, 0><<<dim3(6, NROWS / 128), 256, GEMM_SMEM>>>(vh, vl, wqh, wql, bq, qs);
    // 7: last transpose
    transpose_split<<<dim3(CI_ / 32, CT_ / 32), 256>>>(Wv, wvh, wvl, CT_, CI_);
    // 8-9: K/V projections
    gemm_mma<512, 0><<<dim3(6, KVROWS / 128), 256, GEMM_SMEM>>>(th, tl, wkh, wkl, bk, ks);
    gemm_mma<512, 0><<<dim3(6, KVROWS / 128), 256, GEMM_SMEM>>>(th, tl, wvh, wvl, bv, vsc);
    // 10: attention + residual -> fused hi/lo
    attn_kernel<<<dim3(12, B_), 256>>>(qs, ks, vsc, vis, fh, fl);
    // 11: MLP1 with gelu epilogue
    gemm_mma<768, 1><<<dim3(6, NROWS / 128), 256, GEMM_SMEM>>>(fh, fl, w1h, w1l, b1, hs);
    // 12-13: thin head + rel tail
    logits_kernel<<<(NROWS * 32 + 255) / 256, 256>>>(hs, W2, b2, out);
    fill_rel<<<(NROWS + 255) / 256, 256>>>(out + (size_t)NROWS * 2);
}

// round 5
// speedup vs baseline: 1.0344x; 1.0344x over previous
#include <cuda_runtime.h>
#include <cuda_bf16.h>
#include <cstdint>

// Problem constants
#define B_   256
#define NV_  196
#define LT_  32
#define CI_  768
#define CT_  512
#define NROWS (B_*NV_)      // 50176
#define KVROWS (B_*LT_)     // 8192
#define KVW   1536          // fused K|V output width

// -------------------- scratch (device globals; no allocation) --------------------
__device__ __nv_bfloat16 g_vis_hi [(size_t)NROWS * CI_];
__device__ __nv_bfloat16 g_vis_lo [(size_t)NROWS * CI_];
__device__ __nv_bfloat16 g_text_hi[(size_t)KVROWS * CT_];
__device__ __nv_bfloat16 g_text_lo[(size_t)KVROWS * CT_];
__device__ __nv_bfloat16 g_wqT_hi [(size_t)CI_ * CI_];
__device__ __nv_bfloat16 g_wqT_lo [(size_t)CI_ * CI_];
__device__ __nv_bfloat16 g_wkvT_hi[(size_t)KVW * CT_];
__device__ __nv_bfloat16 g_wkvT_lo[(size_t)KVW * CT_];
__device__ __nv_bfloat16 g_w1T_hi [(size_t)CI_ * CI_];
__device__ __nv_bfloat16 g_w1T_lo [(size_t)CI_ * CI_];
__device__ __nv_bfloat16 g_fused_hi[(size_t)NROWS * CI_];
__device__ __nv_bfloat16 g_fused_lo[(size_t)NROWS * CI_];
__device__ float g_q  [(size_t)NROWS * CI_];
__device__ float g_kv [(size_t)KVROWS * KVW];
__device__ float g_bkv[KVW];
__device__ float g_part[(size_t)6 * NROWS * 2];

// -------------------- small helpers --------------------
__device__ __forceinline__ float qgelu(float x) {
    return x / (1.0f + __expf(-1.702f * x));
}
__device__ __forceinline__ void split_bf(float x, __nv_bfloat16& h, __nv_bfloat16& l) {
    h = __float2bfloat16(x);
    l = __float2bfloat16(x - __bfloat162float(h));
}
__device__ __forceinline__ uint32_t pack_bf2(__nv_bfloat16 a, __nv_bfloat16 b) {
    uint32_t la = (uint32_t)__bfloat16_as_ushort(a);
    uint32_t lb = (uint32_t)__bfloat16_as_ushort(b);
    return la | (lb << 16);
}
__device__ __forceinline__ uint32_t smem_u32(const void* p) {
    uint32_t a;
    asm("{ .reg .u64 t; cvta.to.shared.u64 t, %1; cvt.u32.u64 %0, t; }" : "=r"(a) : "l"(p));
    return a;
}

// -------------------- mma / ldmatrix / cp.async primitives (base sm_103) --------
__device__ __forceinline__ void ldsm_x4(uint32_t* r, uint32_t addr) {
    asm volatile("ldmatrix.sync.aligned.m8n8.x4.shared.b16 {%0,%1,%2,%3}, [%4];"
                 : "=r"(r[0]), "=r"(r[1]), "=r"(r[2]), "=r"(r[3]) : "r"(addr));
}
__device__ __forceinline__ void mma_bf16(float* d, const uint32_t* a, const uint32_t* b) {
    asm volatile(
        "mma.sync.aligned.m16n8k16.row.col.f32.bf16.bf16.f32 "
        "{%0,%1,%2,%3}, {%4,%5,%6,%7}, {%8,%9}, {%0,%1,%2,%3};"
        : "+f"(d[0]), "+f"(d[1]), "+f"(d[2]), "+f"(d[3])
        : "r"(a[0]), "r"(a[1]), "r"(a[2]), "r"(a[3]), "r"(b[0]), "r"(b[1]));
}
__device__ __forceinline__ void cp_async16(uint32_t dst, const void* src) {
    asm volatile("cp.async.ca.shared.global [%0], [%1], 16;" :: "r"(dst), "l"(src));
}
__device__ __forceinline__ void cp_commit() {
    asm volatile("cp.async.commit_group;");
}
__device__ __forceinline__ void cp_wait1() {
    asm volatile("cp.async.wait_group 1;");
}

// -------------------- bf16x3 tensor-core GEMM --------------------
// Tile 128x128x32, 256 threads, 3-stage cp.async pipeline.
// DO_HEAD: apply bias+gelu in regs, dot vs W2, emit per-block partial logits
// (no C write). Otherwise: C = acc + bias.
#define SST 40
#define TILE_B (128 * SST * 2)
#define STAGE_B (4 * TILE_B)
#define GEMM_SMEM (3 * STAGE_B)     // 122880 bytes

__device__ __forceinline__ void issue_tile(uint32_t dst, const __nv_bfloat16* src,
                                           int ld, int tid) {
#pragma unroll
    for (int it = 0; it < 2; it++) {
        int id = tid + it * 256;
        int r = id >> 2, c = id & 3;
        cp_async16(dst + r * (SST * 2) + c * 16, src + (size_t)r * ld + c * 8);
    }
}

template<int KDIM, int OUTN, int DO_HEAD>
__global__ __launch_bounds__(256, 1)
void gemm_mma(const __nv_bfloat16* __restrict__ Ahi, const __nv_bfloat16* __restrict__ Alo,
              const __nv_bfloat16* __restrict__ Bhi, const __nv_bfloat16* __restrict__ Blo,
              const float* __restrict__ bias, float* __restrict__ C,
              const float* __restrict__ W2p, float* __restrict__ part) {
    extern __shared__ char smem[];
    const int tid = threadIdx.x;
    const int lane = tid & 31;
    const int wid = tid >> 5;
    const int wm = wid & 3;
    const int wn = wid >> 2;
    const int n0 = blockIdx.x * 128;
    const int m0 = blockIdx.y * 128;

    const uint32_t sbase = smem_u32(smem);

    const __nv_bfloat16* Ah = Ahi + (size_t)m0 * KDIM;
    const __nv_bfloat16* Al = Alo + (size_t)m0 * KDIM;
    const __nv_bfloat16* Bh = Bhi + (size_t)n0 * KDIM;
    const __nv_bfloat16* Bl = Blo + (size_t)n0 * KDIM;

    constexpr int NC = KDIM / 32;

    float acc[2][8][4];
#pragma unroll
    for (int i = 0; i < 2; i++)
#pragma unroll
        for (int j = 0; j < 8; j++)
#pragma unroll
            for (int k = 0; k < 4; k++) acc[i][j][k] = 0.f;

#pragma unroll
    for (int p = 0; p < 2; p++) {
        uint32_t st = sbase + p * STAGE_B;
        issue_tile(st,              Ah + p * 32, KDIM, tid);
        issue_tile(st + TILE_B,     Al + p * 32, KDIM, tid);
        issue_tile(st + 2 * TILE_B, Bh + p * 32, KDIM, tid);
        issue_tile(st + 3 * TILE_B, Bl + p * 32, KDIM, tid);
        cp_commit();
    }

    const int a_row = wm * 32 + (lane & 15);
    const int a_colb = ((lane >> 4) << 3) * 2;
    const int b_row = wn * 64 + (lane & 7) + ((lane >> 4) << 3);
    const int b_colb = (((lane >> 3) & 1) << 3) * 2;

    for (int c = 0; c < NC; c++) {
        cp_wait1();
        __syncthreads();
        if (c + 2 < NC) {
            uint32_t st = sbase + ((c + 2) % 3) * STAGE_B;
            int k0 = (c + 2) * 32;
            issue_tile(st,              Ah + k0, KDIM, tid);
            issue_tile(st + TILE_B,     Al + k0, KDIM, tid);
            issue_tile(st + 2 * TILE_B, Bh + k0, KDIM, tid);
            issue_tile(st + 3 * TILE_B, Bl + k0, KDIM, tid);
        }
        cp_commit();

        uint32_t st = sbase + (c % 3) * STAGE_B;
#pragma unroll
        for (int ks = 0; ks < 2; ks++) {
            const int kb = ks * 32;
            uint32_t Ahf[2][4], Alf[2][4];
#pragma unroll
            for (int mi = 0; mi < 2; mi++) {
                uint32_t arow = (a_row + mi * 16) * (SST * 2) + kb + a_colb;
                ldsm_x4(Ahf[mi], st + arow);
                ldsm_x4(Alf[mi], st + TILE_B + arow);
            }
            uint32_t Bhf[4][4], Blf[4][4];
#pragma unroll
            for (int ni2 = 0; ni2 < 4; ni2++) {
                uint32_t brow = (b_row + ni2 * 16) * (SST * 2) + kb + b_colb;
                ldsm_x4(Bhf[ni2], st + 2 * TILE_B + brow);
                ldsm_x4(Blf[ni2], st + 3 * TILE_B + brow);
            }
#pragma unroll
            for (int mi = 0; mi < 2; mi++)
#pragma unroll
                for (int ni = 0; ni < 8; ni++) {
                    const int ni2 = ni >> 1, od = (ni & 1) * 2;
                    mma_bf16(acc[mi][ni], Ahf[mi], &Bhf[ni2][od]);
                    mma_bf16(acc[mi][ni], Ahf[mi], &Blf[ni2][od]);
                    mma_bf16(acc[mi][ni], Alf[mi], &Bhf[ni2][od]);
                }
        }
        // NOTE: no trailing __syncthreads needed with 3 stages: the sync at the
        // top of iter c+1 orders this compute before stage (c+3)%3 = c%3 reuse.
    }

    if (!DO_HEAD) {
#pragma unroll
        for (int mi = 0; mi < 2; mi++) {
            int row0 = m0 + wm * 32 + mi * 16 + (lane >> 2);
#pragma unroll
            for (int ni = 0; ni < 8; ni++) {
                int col = n0 + wn * 64 + ni * 8 + (lane & 3) * 2;
                float b0 = bias[col], b1 = bias[col + 1];
                *(float2*)(C + (size_t)row0 * OUTN + col) =
                    make_float2(acc[mi][ni][0] + b0, acc[mi][ni][1] + b1);
                *(float2*)(C + (size_t)(row0 + 8) * OUTN + col) =
                    make_float2(acc[mi][ni][2] + b0, acc[mi][ni][3] + b1);
            }
        }
    } else {
        // fused head: p[row][2] = sum_cols qgelu(acc + b1[col]) * W2[col][:]
        __syncthreads();           // smem tiles no longer needed -> reuse as red
        float* red = (float*)smem; // 128 rows x 2 floats
        const float2* w2 = (const float2*)W2p;
#pragma unroll
        for (int mi = 0; mi < 2; mi++) {
            float pa0 = 0.f, pa1 = 0.f, pb0 = 0.f, pb1 = 0.f;
#pragma unroll
            for (int ni = 0; ni < 8; ni++) {
                int col = n0 + wn * 64 + ni * 8 + (lane & 3) * 2;
                float b0 = bias[col], b1 = bias[col + 1];
                float v0 = qgelu(acc[mi][ni][0] + b0);
                float v1 = qgelu(acc[mi][ni][1] + b1);
                float v2 = qgelu(acc[mi][ni][2] + b0);
                float v3 = qgelu(acc[mi][ni][3] + b1);
                float2 wA = w2[col], wB = w2[col + 1];
                pa0 += v0 * wA.x + v1 * wB.x;
                pa1 += v0 * wA.y + v1 * wB.y;
                pb0 += v2 * wA.x + v3 * wB.x;
                pb1 += v2 * wA.y + v3 * wB.y;
            }
            // reduce over the 4 lanes (lane&3) sharing a row
#pragma unroll
            for (int off = 1; off <= 2; off <<= 1) {
                pa0 += __shfl_xor_sync(0xffffffffu, pa0, off);
                pa1 += __shfl_xor_sync(0xffffffffu, pa1, off);
                pb0 += __shfl_xor_sync(0xffffffffu, pb0, off);
                pb1 += __shfl_xor_sync(0xffffffffu, pb1, off);
            }
            if ((lane & 3) == 0) {
                int lrA = wm * 32 + mi * 16 + (lane >> 2);
                if (wn == 0) {
                    red[lrA * 2]           = pa0;
                    red[lrA * 2 + 1]       = pa1;
                    red[(lrA + 8) * 2]     = pb0;
                    red[(lrA + 8) * 2 + 1] = pb1;
                }
            }
        }
        __syncthreads();
        if (wn == 1 && (lane & 3) == 0) {
            // recompute and add (second half of columns) -- note: done via second
            // pass accumulate to avoid races
        }
        // second warpgroup adds its contribution
#pragma unroll
        for (int mi = 0; mi < 2; mi++) {
            if (wn == 1) {
                float pa0 = 0.f, pa1 = 0.f, pb0 = 0.f, pb1 = 0.f;
#pragma unroll
                for (int ni = 0; ni < 8; ni++) {
                    int col = n0 + wn * 64 + ni * 8 + (lane & 3) * 2;
                    float b0 = bias[col], b1 = bias[col + 1];
                    float v0 = qgelu(acc[mi][ni][0] + b0);
                    float v1 = qgelu(acc[mi][ni][1] + b1);
                    float v2 = qgelu(acc[mi][ni][2] + b0);
                    float v3 = qgelu(acc[mi][ni][3] + b1);
                    float2 wA = w2[col], wB = w2[col + 1];
                    pa0 += v0 * wA.x + v1 * wB.x;
                    pa1 += v0 * wA.y + v1 * wB.y;
                    pb0 += v2 * wA.x + v3 * wB.x;
                    pb1 += v2 * wA.y + v3 * wB.y;
                }
#pragma unroll
                for (int off = 1; off <= 2; off <<= 1) {
                    pa0 += __shfl_xor_sync(0xffffffffu, pa0, off);
                    pa1 += __shfl_xor_sync(0xffffffffu, pa1, off);
                    pb0 += __shfl_xor_sync(0xffffffffu, pb0, off);
                    pb1 += __shfl_xor_sync(0xffffffffu, pb1, off);
                }
                if ((lane & 3) == 0) {
                    int lrA = wm * 32 + mi * 16 + (lane >> 2);
                    red[lrA * 2]           += pa0;
                    red[lrA * 2 + 1]       += pa1;
                    red[(lrA + 8) * 2]     += pb0;
                    red[(lrA + 8) * 2 + 1] += pb1;
                }
            }
        }
        __syncthreads();
        // write partials: 256 values
        int row = tid >> 1, comp = tid & 1;
        part[((size_t)blockIdx.x * NROWS + m0 + row) * 2 + comp] = red[row * 2 + comp];
    }
}

// -------------------- elementwise fp32 -> bf16 hi/lo split --------------------
__global__ __launch_bounds__(256)
void split_kernel(const float* __restrict__ x, __nv_bfloat16* __restrict__ hi,
                  __nv_bfloat16* __restrict__ lo, int n4) {
    int i = blockIdx.x * blockDim.x + threadIdx.x;
    if (i >= n4) return;
    float4 v = ((const float4*)x)[i];
    __nv_bfloat16 h0, h1, h2, h3, l0, l1, l2, l3;
    split_bf(v.x, h0, l0);
    split_bf(v.y, h1, l1);
    split_bf(v.z, h2, l2);
    split_bf(v.w, h3, l3);
    ((uint2*)hi)[i] = make_uint2(pack_bf2(h0, h1), pack_bf2(h2, h3));
    ((uint2*)lo)[i] = make_uint2(pack_bf2(l0, l1), pack_bf2(l2, l3));
}

// -------------------- weight transpose + split: W[K,N] -> T[N,K] hi/lo --------
__global__ __launch_bounds__(256)
void transpose_split(const float* __restrict__ W, __nv_bfloat16* __restrict__ Thi,
                     __nv_bfloat16* __restrict__ Tlo, int K, int N) {
    __shared__ float t[32][33];
    int n0 = blockIdx.x * 32, k0 = blockIdx.y * 32;
    int tx = threadIdx.x & 31, ty = threadIdx.x >> 5;
#pragma unroll
    for (int s = 0; s < 4; s++)
        t[ty + 8 * s][tx] = W[(size_t)(k0 + ty + 8 * s) * N + n0 + tx];
    __syncthreads();
#pragma unroll
    for (int s = 0; s < 4; s++) {
        int n = n0 + ty + 8 * s;
        int k = k0 + tx;
        float v = t[tx][ty + 8 * s];
        __nv_bfloat16 h, l;
        split_bf(v, h, l);
        Thi[(size_t)n * K + k] = h;
        Tlo[(size_t)n * K + k] = l;
    }
}

// -------------------- bias concat for fused KV --------------------
__global__ void concat_bias(const float* __restrict__ bk, const float* __restrict__ bv,
                            float* __restrict__ bkv) {
    int i = blockIdx.x * blockDim.x + threadIdx.x;
    if (i < 768) bkv[i] = bk[i];
    else if (i < 1536) bkv[i] = bv[i - 768];
}

// -------------------- attention (R3 version); reads fused g_kv ----------------
__global__ __launch_bounds__(256)
void attn_kernel(const float* __restrict__ q_s, const float* __restrict__ kv,
                 const float* __restrict__ vis,
                 __nv_bfloat16* __restrict__ f_hi, __nv_bfloat16* __restrict__ f_lo) {
    int h = blockIdx.x;
    int b = blockIdx.y;
    __shared__ float4 ksm[32][16];
    __shared__ float4 vsm[32][16];
    int tid = threadIdx.x;

    const float* kbase = kv + (size_t)b * 32 * KVW + h * 64;
    const float* vbase = kbase + 768;
    for (int i = tid; i < 512; i += 256) {
        int l = i >> 4, d4 = i & 15;
        ksm[l][d4] = *(const float4*)(kbase + (size_t)l * KVW + d4 * 4);
        vsm[l][d4] = *(const float4*)(vbase + (size_t)l * KVW + d4 * 4);
    }
    __syncthreads();

    int n = tid;
    if (n >= 196) return;
    size_t rowoff = (size_t)(b * 196 + n) * 768 + h * 64;
    const float4* qrow = (const float4*)(q_s + rowoff);
    float4 q4[16];
#pragma unroll
    for (int d = 0; d < 16; d++) q4[d] = qrow[d];

    float s[32];
#pragma unroll
    for (int l = 0; l < 32; l++) {
        float ax = 0.f, ay = 0.f, az = 0.f, aw = 0.f;
#pragma unroll
        for (int d = 0; d < 16; d++) {
            float4 kk = ksm[l][d];
            ax += q4[d].x * kk.x;
            ay += q4[d].y * kk.y;
            az += q4[d].z * kk.z;
            aw += q4[d].w * kk.w;
        }
        s[l] = (ax + ay + az + aw) * 0.125f;
    }
    float m = s[0];
#pragma unroll
    for (int l = 1; l < 32; l++) m = fmaxf(m, s[l]);
    float sum = 0.f;
#pragma unroll
    for (int l = 0; l < 32; l++) { s[l] = __expf(s[l] - m); sum += s[l]; }
    float inv = 1.0f / sum;

    const float4* visrow = (const float4*)(vis + rowoff);
    uint2* hrow = (uint2*)(f_hi + rowoff);
    uint2* lrow = (uint2*)(f_lo + rowoff);
    for (int d = 0; d < 16; d++) {
        float ax = 0.f, ay = 0.f, az = 0.f, aw = 0.f;
#pragma unroll
        for (int l = 0; l < 32; l++) {
            float4 vv = vsm[l][d];
            float p = s[l];
            ax += p * vv.x;
            ay += p * vv.y;
            az += p * vv.z;
            aw += p * vv.w;
        }
        float4 r = visrow[d];
        float o0 = ax * inv + r.x;
        float o1 = ay * inv + r.y;
        float o2 = az * inv + r.z;
        float o3 = aw * inv + r.w;
        __nv_bfloat16 h0, h1, h2, h3, l0, l1, l2, l3;
        split_bf(o0, h0, l0);
        split_bf(o1, h1, l1);
        split_bf(o2, h2, l2);
        split_bf(o3, h3, l3);
        hrow[d] = make_uint2(pack_bf2(h0, h1), pack_bf2(h2, h3));
        lrow[d] = make_uint2(pack_bf2(l0, l1), pack_bf2(l2, l3));
    }
}

// -------------------- head reduce: sum 6 partials + bias; fill rel -------------
__global__ __launch_bounds__(256)
void reduce_head(const float* __restrict__ part, const float* __restrict__ b2,
                 float* __restrict__ out) {
    int i = blockIdx.x * blockDim.x + threadIdx.x;
    if (i >= NROWS) return;
    float a0 = b2[0], a1 = b2[1];
#pragma unroll
    for (int p = 0; p < 6; p++) {
        a0 += part[((size_t)p * NROWS + i) * 2];
        a1 += part[((size_t)p * NROWS + i) * 2 + 1];
    }
    out[(size_t)i * 2]     = a0;
    out[(size_t)i * 2 + 1] = a1;
    out[(size_t)NROWS * 2 + i] = 1.0f / 32.0f;   // rel_BN == 1/Lt exactly
}

// -------------------- host launch --------------------
extern "C" void kernel_launch(void* const* d_in, const int* in_sizes, int n_in,
                              void* d_out, int out_size) {
    const float* vis  = (const float*)d_in[0];
    const float* text = (const float*)d_in[1];
    const float* Wq   = (const float*)d_in[2];
    const float* bq   = (const float*)d_in[3];
    const float* Wk   = (const float*)d_in[4];
    const float* bk   = (const float*)d_in[5];
    const float* Wv   = (const float*)d_in[6];
    const float* bv   = (const float*)d_in[7];
    const float* W1   = (const float*)d_in[8];
    const float* b1   = (const float*)d_in[9];
    const float* W2   = (const float*)d_in[10];
    const float* b2   = (const float*)d_in[11];
    float* out = (float*)d_out;

    __nv_bfloat16 *vh, *vl, *th, *tl, *wqh, *wql, *wkvh, *wkvl, *w1h, *w1l, *fh, *fl;
    float *qs, *kvs, *bkv, *partp;
    cudaGetSymbolAddress((void**)&vh,   g_vis_hi);
    cudaGetSymbolAddress((void**)&vl,   g_vis_lo);
    cudaGetSymbolAddress((void**)&th,   g_text_hi);
    cudaGetSymbolAddress((void**)&tl,   g_text_lo);
    cudaGetSymbolAddress((void**)&wqh,  g_wqT_hi);
    cudaGetSymbolAddress((void**)&wql,  g_wqT_lo);
    cudaGetSymbolAddress((void**)&wkvh, g_wkvT_hi);
    cudaGetSymbolAddress((void**)&wkvl, g_wkvT_lo);
    cudaGetSymbolAddress((void**)&w1h,  g_w1T_hi);
    cudaGetSymbolAddress((void**)&w1l,  g_w1T_lo);
    cudaGetSymbolAddress((void**)&fh,   g_fused_hi);
    cudaGetSymbolAddress((void**)&fl,   g_fused_lo);
    cudaGetSymbolAddress((void**)&qs,   g_q);
    cudaGetSymbolAddress((void**)&kvs,  g_kv);
    cudaGetSymbolAddress((void**)&bkv,  g_bkv);
    cudaGetSymbolAddress((void**)&partp, g_part);

    cudaFuncSetAttribute(gemm_mma<768, 768, 0>,  cudaFuncAttributeMaxDynamicSharedMemorySize, GEMM_SMEM);
    cudaFuncSetAttribute(gemm_mma<512, KVW, 0>,  cudaFuncAttributeMaxDynamicSharedMemorySize, GEMM_SMEM);
    cudaFuncSetAttribute(gemm_mma<768, 768, 1>,  cudaFuncAttributeMaxDynamicSharedMemorySize, GEMM_SMEM);

    // 1: split vis
    {
        int n4 = NROWS * CI_ / 4;
        split_kernel<<<(n4 + 255) / 256, 256>>>(vis, vh, vl, n4);
    }
    // 2: split text
    {
        int n4 = KVROWS * CT_ / 4;
        split_kernel<<<(n4 + 255) / 256, 256>>>(text, th, tl, n4);
    }
    // 3: transpose Wq
    transpose_split<<<dim3(CI_ / 32, CI_ / 32), 256>>>(Wq, wqh, wql, CI_, CI_);
    // 4: Q projection  <-- profiler slot
    gemm_mma<768, 768, 0><<<dim3(6, NROWS / 128), 256, GEMM_SMEM>>>(
        vh, vl, wqh, wql, bq, qs, nullptr, nullptr);
    // 5-6: transpose Wk, Wv into fused wkv (rows 0-767 and 768-1535)
    transpose_split<<<dim3(CI_ / 32, CT_ / 32), 256>>>(Wk, wkvh, wkvl, CT_, CI_);
    transpose_split<<<dim3(CI_ / 32, CT_ / 32), 256>>>(
        Wv, wkvh + (size_t)768 * CT_, wkvl + (size_t)768 * CT_, CT_, CI_);
    // 7: bias concat
    concat_bias<<<6, 256>>>(bk, bv, bkv);
    // 8: fused K|V projection
    gemm_mma<512, KVW, 0><<<dim3(12, KVROWS / 128), 256, GEMM_SMEM>>>(
        th, tl, wkvh, wkvl, bkv, kvs, nullptr, nullptr);
    // 9: attention + residual -> fused hi/lo
    attn_kernel<<<dim3(12, B_), 256>>>(qs, kvs, vis, fh, fl);
    // 10: transpose W1
    transpose_split<<<dim3(CI_ / 32, CI_ / 32), 256>>>(W1, w1h, w1l, CI_, CI_);
    // 11: MLP1 + gelu + fused W2 head -> partials
    gemm_mma<768, 768, 1><<<dim3(6, NROWS / 128), 256, GEMM_SMEM>>>(
        fh, fl, w1h, w1l, b1, nullptr, W2, partp);
    // 12: reduce partials + bias; fill rel
    reduce_head<<<(NROWS + 255) / 256, 256>>>(partp, b2, out);
}

// round 6
// speedup vs baseline: 1.1880x; 1.1485x over previous
#include <cuda_runtime.h>
#include <cuda_bf16.h>
#include <cstdint>

// Problem constants
#define B_   256
#define NV_  196
#define LT_  32
#define CI_  768
#define CT_  512
#define NROWS (B_*NV_)      // 50176
#define KVROWS (B_*LT_)     // 8192
#define KVW   1536          // fused K|V output width

// -------------------- scratch (device globals; no allocation) --------------------
__device__ __nv_bfloat16 g_vis_hi [(size_t)NROWS * CI_];
__device__ __nv_bfloat16 g_vis_lo [(size_t)NROWS * CI_];
__device__ __nv_bfloat16 g_text_hi[(size_t)KVROWS * CT_];
__device__ __nv_bfloat16 g_text_lo[(size_t)KVROWS * CT_];
__device__ __nv_bfloat16 g_wqT_hi [(size_t)CI_ * CI_];
__device__ __nv_bfloat16 g_wqT_lo [(size_t)CI_ * CI_];
__device__ __nv_bfloat16 g_wkvT_hi[(size_t)KVW * CT_];
__device__ __nv_bfloat16 g_wkvT_lo[(size_t)KVW * CT_];
__device__ __nv_bfloat16 g_w1T_hi [(size_t)CI_ * CI_];
__device__ __nv_bfloat16 g_w1T_lo [(size_t)CI_ * CI_];
__device__ __nv_bfloat16 g_fused_hi[(size_t)NROWS * CI_];
__device__ __nv_bfloat16 g_fused_lo[(size_t)NROWS * CI_];
__device__ float g_q  [(size_t)NROWS * CI_];
__device__ float g_kv [(size_t)KVROWS * KVW];
__device__ float g_bkv[KVW];
__device__ float g_part[(size_t)6 * NROWS * 2];

// -------------------- small helpers --------------------
__device__ __forceinline__ float qgelu(float x) {
    return x / (1.0f + __expf(-1.702f * x));
}
__device__ __forceinline__ void split_bf(float x, __nv_bfloat16& h, __nv_bfloat16& l) {
    h = __float2bfloat16(x);
    l = __float2bfloat16(x - __bfloat162float(h));
}
__device__ __forceinline__ uint32_t pack_bf2(__nv_bfloat16 a, __nv_bfloat16 b) {
    uint32_t la = (uint32_t)__bfloat16_as_ushort(a);
    uint32_t lb = (uint32_t)__bfloat16_as_ushort(b);
    return la | (lb << 16);
}
__device__ __forceinline__ uint32_t smem_u32(const void* p) {
    uint32_t a;
    asm("{ .reg .u64 t; cvta.to.shared.u64 t, %1; cvt.u32.u64 %0, t; }" : "=r"(a) : "l"(p));
    return a;
}

// -------------------- mma / ldmatrix / cp.async primitives (base sm_103) --------
__device__ __forceinline__ void ldsm_x4(uint32_t* r, uint32_t addr) {
    asm volatile("ldmatrix.sync.aligned.m8n8.x4.shared.b16 {%0,%1,%2,%3}, [%4];"
                 : "=r"(r[0]), "=r"(r[1]), "=r"(r[2]), "=r"(r[3]) : "r"(addr));
}
__device__ __forceinline__ void mma_bf16(float* d, const uint32_t* a, const uint32_t* b) {
    asm volatile(
        "mma.sync.aligned.m16n8k16.row.col.f32.bf16.bf16.f32 "
        "{%0,%1,%2,%3}, {%4,%5,%6,%7}, {%8,%9}, {%0,%1,%2,%3};"
        : "+f"(d[0]), "+f"(d[1]), "+f"(d[2]), "+f"(d[3])
        : "r"(a[0]), "r"(a[1]), "r"(a[2]), "r"(a[3]), "r"(b[0]), "r"(b[1]));
}
__device__ __forceinline__ void cp_async16(uint32_t dst, const void* src) {
    asm volatile("cp.async.ca.shared.global [%0], [%1], 16;" :: "r"(dst), "l"(src));
}
__device__ __forceinline__ void cp_commit() {
    asm volatile("cp.async.commit_group;");
}
__device__ __forceinline__ void cp_wait0() {
    asm volatile("cp.async.wait_group 0;");
}

// -------------------- bf16x3 tensor-core GEMM --------------------
// Tile 128x128x32, 256 threads, 2-stage cp.async pipeline, 2 CTAs/SM.
#define SST 40
#define TILE_B (128 * SST * 2)
#define STAGE_B (4 * TILE_B)
#define GEMM_SMEM (2 * STAGE_B)     // 81920 bytes -> 2 CTAs/SM

__device__ __forceinline__ void issue_tile(uint32_t dst, const __nv_bfloat16* src,
                                           int ld, int tid) {
#pragma unroll
    for (int it = 0; it < 2; it++) {
        int id = tid + it * 256;
        int r = id >> 2, c = id & 3;
        cp_async16(dst + r * (SST * 2) + c * 16, src + (size_t)r * ld + c * 8);
    }
}

template<int KDIM, int OUTN, int DO_HEAD>
__global__ __launch_bounds__(256, 2)
void gemm_mma(const __nv_bfloat16* __restrict__ Ahi, const __nv_bfloat16* __restrict__ Alo,
              const __nv_bfloat16* __restrict__ Bhi, const __nv_bfloat16* __restrict__ Blo,
              const float* __restrict__ bias, float* __restrict__ C,
              const float* __restrict__ W2p, float* __restrict__ part) {
    extern __shared__ char smem[];
    const int tid = threadIdx.x;
    const int lane = tid & 31;
    const int wid = tid >> 5;
    const int wm = wid & 3;
    const int wn = wid >> 2;
    const int n0 = blockIdx.x * 128;
    const int m0 = blockIdx.y * 128;

    const uint32_t sbase = smem_u32(smem);

    const __nv_bfloat16* Ah = Ahi + (size_t)m0 * KDIM;
    const __nv_bfloat16* Al = Alo + (size_t)m0 * KDIM;
    const __nv_bfloat16* Bh = Bhi + (size_t)n0 * KDIM;
    const __nv_bfloat16* Bl = Blo + (size_t)n0 * KDIM;

    constexpr int NC = KDIM / 32;

    float acc[2][8][4];
#pragma unroll
    for (int i = 0; i < 2; i++)
#pragma unroll
        for (int j = 0; j < 8; j++)
#pragma unroll
            for (int k = 0; k < 4; k++) acc[i][j][k] = 0.f;

    // prologue: chunk 0 -> stage 0
    {
        uint32_t st = sbase;
        issue_tile(st,              Ah, KDIM, tid);
        issue_tile(st + TILE_B,     Al, KDIM, tid);
        issue_tile(st + 2 * TILE_B, Bh, KDIM, tid);
        issue_tile(st + 3 * TILE_B, Bl, KDIM, tid);
        cp_commit();
    }

    const int a_row = wm * 32 + (lane & 15);
    const int a_colb = ((lane >> 4) << 3) * 2;
    const int b_row = wn * 64 + (lane & 7) + ((lane >> 4) << 3);
    const int b_colb = (((lane >> 3) & 1) << 3) * 2;

    for (int c = 0; c < NC; c++) {
        cp_wait0();          // chunk c resident
        __syncthreads();     // all warps done with stage (c+1)&1 from iter c-1
        if (c + 1 < NC) {
            uint32_t st = sbase + ((c + 1) & 1) * STAGE_B;
            int k0 = (c + 1) * 32;
            issue_tile(st,              Ah + k0, KDIM, tid);
            issue_tile(st + TILE_B,     Al + k0, KDIM, tid);
            issue_tile(st + 2 * TILE_B, Bh + k0, KDIM, tid);
            issue_tile(st + 3 * TILE_B, Bl + k0, KDIM, tid);
            cp_commit();
        }

        uint32_t st = sbase + (c & 1) * STAGE_B;
#pragma unroll
        for (int ks = 0; ks < 2; ks++) {
            const int kb = ks * 32;
            uint32_t Ahf[2][4], Alf[2][4];
#pragma unroll
            for (int mi = 0; mi < 2; mi++) {
                uint32_t arow = (a_row + mi * 16) * (SST * 2) + kb + a_colb;
                ldsm_x4(Ahf[mi], st + arow);
                ldsm_x4(Alf[mi], st + TILE_B + arow);
            }
            uint32_t Bhf[4][4], Blf[4][4];
#pragma unroll
            for (int ni2 = 0; ni2 < 4; ni2++) {
                uint32_t brow = (b_row + ni2 * 16) * (SST * 2) + kb + b_colb;
                ldsm_x4(Bhf[ni2], st + 2 * TILE_B + brow);
                ldsm_x4(Blf[ni2], st + 3 * TILE_B + brow);
            }
#pragma unroll
            for (int mi = 0; mi < 2; mi++)
#pragma unroll
                for (int ni = 0; ni < 8; ni++) {
                    const int ni2 = ni >> 1, od = (ni & 1) * 2;
                    mma_bf16(acc[mi][ni], Ahf[mi], &Bhf[ni2][od]);
                    mma_bf16(acc[mi][ni], Ahf[mi], &Blf[ni2][od]);
                    mma_bf16(acc[mi][ni], Alf[mi], &Bhf[ni2][od]);
                }
        }
    }

    if (!DO_HEAD) {
#pragma unroll
        for (int mi = 0; mi < 2; mi++) {
            int row0 = m0 + wm * 32 + mi * 16 + (lane >> 2);
#pragma unroll
            for (int ni = 0; ni < 8; ni++) {
                int col = n0 + wn * 64 + ni * 8 + (lane & 3) * 2;
                float b0 = bias[col], b1 = bias[col + 1];
                *(float2*)(C + (size_t)row0 * OUTN + col) =
                    make_float2(acc[mi][ni][0] + b0, acc[mi][ni][1] + b1);
                *(float2*)(C + (size_t)(row0 + 8) * OUTN + col) =
                    make_float2(acc[mi][ni][2] + b0, acc[mi][ni][3] + b1);
            }
        }
    } else {
        // fused head: p[row][2] = sum_cols qgelu(acc + b1[col]) * W2[col][:]
        __syncthreads();
        float* red = (float*)smem;
        const float2* w2 = (const float2*)W2p;
#pragma unroll
        for (int mi = 0; mi < 2; mi++) {
            float pa0 = 0.f, pa1 = 0.f, pb0 = 0.f, pb1 = 0.f;
#pragma unroll
            for (int ni = 0; ni < 8; ni++) {
                int col = n0 + wn * 64 + ni * 8 + (lane & 3) * 2;
                float b0 = bias[col], b1 = bias[col + 1];
                float v0 = qgelu(acc[mi][ni][0] + b0);
                float v1 = qgelu(acc[mi][ni][1] + b1);
                float v2 = qgelu(acc[mi][ni][2] + b0);
                float v3 = qgelu(acc[mi][ni][3] + b1);
                float2 wA = w2[col], wB = w2[col + 1];
                pa0 += v0 * wA.x + v1 * wB.x;
                pa1 += v0 * wA.y + v1 * wB.y;
                pb0 += v2 * wA.x + v3 * wB.x;
                pb1 += v2 * wA.y + v3 * wB.y;
            }
#pragma unroll
            for (int off = 1; off <= 2; off <<= 1) {
                pa0 += __shfl_xor_sync(0xffffffffu, pa0, off);
                pa1 += __shfl_xor_sync(0xffffffffu, pa1, off);
                pb0 += __shfl_xor_sync(0xffffffffu, pb0, off);
                pb1 += __shfl_xor_sync(0xffffffffu, pb1, off);
            }
            if ((lane & 3) == 0 && wn == 0) {
                int lrA = wm * 32 + mi * 16 + (lane >> 2);
                red[lrA * 2]           = pa0;
                red[lrA * 2 + 1]       = pa1;
                red[(lrA + 8) * 2]     = pb0;
                red[(lrA + 8) * 2 + 1] = pb1;
            }
        }
        __syncthreads();
#pragma unroll
        for (int mi = 0; mi < 2; mi++) {
            if (wn == 1) {
                float pa0 = 0.f, pa1 = 0.f, pb0 = 0.f, pb1 = 0.f;
#pragma unroll
                for (int ni = 0; ni < 8; ni++) {
                    int col = n0 + wn * 64 + ni * 8 + (lane & 3) * 2;
                    float b0 = bias[col], b1 = bias[col + 1];
                    float v0 = qgelu(acc[mi][ni][0] + b0);
                    float v1 = qgelu(acc[mi][ni][1] + b1);
                    float v2 = qgelu(acc[mi][ni][2] + b0);
                    float v3 = qgelu(acc[mi][ni][3] + b1);
                    float2 wA = w2[col], wB = w2[col + 1];
                    pa0 += v0 * wA.x + v1 * wB.x;
                    pa1 += v0 * wA.y + v1 * wB.y;
                    pb0 += v2 * wA.x + v3 * wB.x;
                    pb1 += v2 * wA.y + v3 * wB.y;
                }
#pragma unroll
                for (int off = 1; off <= 2; off <<= 1) {
                    pa0 += __shfl_xor_sync(0xffffffffu, pa0, off);
                    pa1 += __shfl_xor_sync(0xffffffffu, pa1, off);
                    pb0 += __shfl_xor_sync(0xffffffffu, pb0, off);
                    pb1 += __shfl_xor_sync(0xffffffffu, pb1, off);
                }
                if ((lane & 3) == 0) {
                    int lrA = wm * 32 + mi * 16 + (lane >> 2);
                    red[lrA * 2]           += pa0;
                    red[lrA * 2 + 1]       += pa1;
                    red[(lrA + 8) * 2]     += pb0;
                    red[(lrA + 8) * 2 + 1] += pb1;
                }
            }
        }
        __syncthreads();
        int row = tid >> 1, comp = tid & 1;
        part[((size_t)blockIdx.x * NROWS + m0 + row) * 2 + comp] = red[row * 2 + comp];
    }
}

// -------------------- elementwise fp32 -> bf16 hi/lo split --------------------
__global__ __launch_bounds__(256)
void split_kernel(const float* __restrict__ x, __nv_bfloat16* __restrict__ hi,
                  __nv_bfloat16* __restrict__ lo, int n4) {
    int i = blockIdx.x * blockDim.x + threadIdx.x;
    if (i >= n4) return;
    float4 v = ((const float4*)x)[i];
    __nv_bfloat16 h0, h1, h2, h3, l0, l1, l2, l3;
    split_bf(v.x, h0, l0);
    split_bf(v.y, h1, l1);
    split_bf(v.z, h2, l2);
    split_bf(v.w, h3, l3);
    ((uint2*)hi)[i] = make_uint2(pack_bf2(h0, h1), pack_bf2(h2, h3));
    ((uint2*)lo)[i] = make_uint2(pack_bf2(l0, l1), pack_bf2(l2, l3));
}

// -------------------- weight transpose + split: W[K,N] -> T[N,K] hi/lo --------
__global__ __launch_bounds__(256)
void transpose_split(const float* __restrict__ W, __nv_bfloat16* __restrict__ Thi,
                     __nv_bfloat16* __restrict__ Tlo, int K, int N) {
    __shared__ float t[32][33];
    int n0 = blockIdx.x * 32, k0 = blockIdx.y * 32;
    int tx = threadIdx.x & 31, ty = threadIdx.x >> 5;
#pragma unroll
    for (int s = 0; s < 4; s++)
        t[ty + 8 * s][tx] = W[(size_t)(k0 + ty + 8 * s) * N + n0 + tx];
    __syncthreads();
#pragma unroll
    for (int s = 0; s < 4; s++) {
        int n = n0 + ty + 8 * s;
        int k = k0 + tx;
        float v = t[tx][ty + 8 * s];
        __nv_bfloat16 h, l;
        split_bf(v, h, l);
        Thi[(size_t)n * K + k] = h;
        Tlo[(size_t)n * K + k] = l;
    }
}

// -------------------- bias concat for fused KV --------------------
__global__ void concat_bias(const float* __restrict__ bk, const float* __restrict__ bv,
                            float* __restrict__ bkv) {
    int i = blockIdx.x * blockDim.x + threadIdx.x;
    if (i < 768) bkv[i] = bk[i];
    else if (i < 1536) bkv[i] = bv[i - 768];
}

// -------------------- attention; reads fused g_kv ----------------
__global__ __launch_bounds__(256)
void attn_kernel(const float* __restrict__ q_s, const float* __restrict__ kv,
                 const float* __restrict__ vis,
                 __nv_bfloat16* __restrict__ f_hi, __nv_bfloat16* __restrict__ f_lo) {
    int h = blockIdx.x;
    int b = blockIdx.y;
    __shared__ float4 ksm[32][16];
    __shared__ float4 vsm[32][16];
    int tid = threadIdx.x;

    const float* kbase = kv + (size_t)b * 32 * KVW + h * 64;
    const float* vbase = kbase + 768;
    for (int i = tid; i < 512; i += 256) {
        int l = i >> 4, d4 = i & 15;
        ksm[l][d4] = *(const float4*)(kbase + (size_t)l * KVW + d4 * 4);
        vsm[l][d4] = *(const float4*)(vbase + (size_t)l * KVW + d4 * 4);
    }
    __syncthreads();

    int n = tid;
    if (n >= 196) return;
    size_t rowoff = (size_t)(b * 196 + n) * 768 + h * 64;
    const float4* qrow = (const float4*)(q_s + rowoff);
    float4 q4[16];
#pragma unroll
    for (int d = 0; d < 16; d++) q4[d] = qrow[d];

    float s[32];
#pragma unroll
    for (int l = 0; l < 32; l++) {
        float ax = 0.f, ay = 0.f, az = 0.f, aw = 0.f;
#pragma unroll
        for (int d = 0; d < 16; d++) {
            float4 kk = ksm[l][d];
            ax += q4[d].x * kk.x;
            ay += q4[d].y * kk.y;
            az += q4[d].z * kk.z;
            aw += q4[d].w * kk.w;
        }
        s[l] = (ax + ay + az + aw) * 0.125f;
    }
    float m = s[0];
#pragma unroll
    for (int l = 1; l < 32; l++) m = fmaxf(m, s[l]);
    float sum = 0.f;
#pragma unroll
    for (int l = 0; l < 32; l++) { s[l] = __expf(s[l] - m); sum += s[l]; }
    float inv = 1.0f / sum;

    const float4* visrow = (const float4*)(vis + rowoff);
    uint2* hrow = (uint2*)(f_hi + rowoff);
    uint2* lrow = (uint2*)(f_lo + rowoff);
    for (int d = 0; d < 16; d++) {
        float ax = 0.f, ay = 0.f, az = 0.f, aw = 0.f;
#pragma unroll
        for (int l = 0; l < 32; l++) {
            float4 vv = vsm[l][d];
            float p = s[l];
            ax += p * vv.x;
            ay += p * vv.y;
            az += p * vv.z;
            aw += p * vv.w;
        }
        float4 r = visrow[d];
        float o0 = ax * inv + r.x;
        float o1 = ay * inv + r.y;
        float o2 = az * inv + r.z;
        float o3 = aw * inv + r.w;
        __nv_bfloat16 h0, h1, h2, h3, l0, l1, l2, l3;
        split_bf(o0, h0, l0);
        split_bf(o1, h1, l1);
        split_bf(o2, h2, l2);
        split_bf(o3, h3, l3);
        hrow[d] = make_uint2(pack_bf2(h0, h1), pack_bf2(h2, h3));
        lrow[d] = make_uint2(pack_bf2(l0, l1), pack_bf2(l2, l3));
    }
}

// -------------------- head reduce: sum 6 partials + bias; fill rel -------------
__global__ __launch_bounds__(256)
void reduce_head(const float* __restrict__ part, const float* __restrict__ b2,
                 float* __restrict__ out) {
    int i = blockIdx.x * blockDim.x + threadIdx.x;
    if (i >= NROWS) return;
    float a0 = b2[0], a1 = b2[1];
#pragma unroll
    for (int p = 0; p < 6; p++) {
        a0 += part[((size_t)p * NROWS + i) * 2];
        a1 += part[((size_t)p * NROWS + i) * 2 + 1];
    }
    out[(size_t)i * 2]     = a0;
    out[(size_t)i * 2 + 1] = a1;
    out[(size_t)NROWS * 2 + i] = 1.0f / 32.0f;   // rel_BN == 1/Lt exactly
}

// -------------------- host launch --------------------
extern "C" void kernel_launch(void* const* d_in, const int* in_sizes, int n_in,
                              void* d_out, int out_size) {
    const float* vis  = (const float*)d_in[0];
    const float* text = (const float*)d_in[1];
    const float* Wq   = (const float*)d_in[2];
    const float* bq   = (const float*)d_in[3];
    const float* Wk   = (const float*)d_in[4];
    const float* bk   = (const float*)d_in[5];
    const float* Wv   = (const float*)d_in[6];
    const float* bv   = (const float*)d_in[7];
    const float* W1   = (const float*)d_in[8];
    const float* b1   = (const float*)d_in[9];
    const float* W2   = (const float*)d_in[10];
    const float* b2   = (const float*)d_in[11];
    float* out = (float*)d_out;

    __nv_bfloat16 *vh, *vl, *th, *tl, *wqh, *wql, *wkvh, *wkvl, *w1h, *w1l, *fh, *fl;
    float *qs, *kvs, *bkv, *partp;
    cudaGetSymbolAddress((void**)&vh,   g_vis_hi);
    cudaGetSymbolAddress((void**)&vl,   g_vis_lo);
    cudaGetSymbolAddress((void**)&th,   g_text_hi);
    cudaGetSymbolAddress((void**)&tl,   g_text_lo);
    cudaGetSymbolAddress((void**)&wqh,  g_wqT_hi);
    cudaGetSymbolAddress((void**)&wql,  g_wqT_lo);
    cudaGetSymbolAddress((void**)&wkvh, g_wkvT_hi);
    cudaGetSymbolAddress((void**)&wkvl, g_wkvT_lo);
    cudaGetSymbolAddress((void**)&w1h,  g_w1T_hi);
    cudaGetSymbolAddress((void**)&w1l,  g_w1T_lo);
    cudaGetSymbolAddress((void**)&fh,   g_fused_hi);
    cudaGetSymbolAddress((void**)&fl,   g_fused_lo);
    cudaGetSymbolAddress((void**)&qs,   g_q);
    cudaGetSymbolAddress((void**)&kvs,  g_kv);
    cudaGetSymbolAddress((void**)&bkv,  g_bkv);
    cudaGetSymbolAddress((void**)&partp, g_part);

    cudaFuncSetAttribute(gemm_mma<768, 768, 0>, cudaFuncAttributeMaxDynamicSharedMemorySize, GEMM_SMEM);
    cudaFuncSetAttribute(gemm_mma<512, KVW, 0>, cudaFuncAttributeMaxDynamicSharedMemorySize, GEMM_SMEM);
    cudaFuncSetAttribute(gemm_mma<768, 768, 1>, cudaFuncAttributeMaxDynamicSharedMemorySize, GEMM_SMEM);

    // 1: split vis
    {
        int n4 = NROWS * CI_ / 4;
        split_kernel<<<(n4 + 255) / 256, 256>>>(vis, vh, vl, n4);
    }
    // 2: split text
    {
        int n4 = KVROWS * CT_ / 4;
        split_kernel<<<(n4 + 255) / 256, 256>>>(text, th, tl, n4);
    }
    // 3: transpose Wq
    transpose_split<<<dim3(CI_ / 32, CI_ / 32), 256>>>(Wq, wqh, wql, CI_, CI_);
    // 4: Q projection  <-- profiler slot
    gemm_mma<768, 768, 0><<<dim3(6, NROWS / 128), 256, GEMM_SMEM>>>(
        vh, vl, wqh, wql, bq, qs, nullptr, nullptr);
    // 5-6: transpose Wk, Wv into fused wkv
    transpose_split<<<dim3(CI_ / 32, CT_ / 32), 256>>>(Wk, wkvh, wkvl, CT_, CI_);
    transpose_split<<<dim3(CI_ / 32, CT_ / 32), 256>>>(
        Wv, wkvh + (size_t)768 * CT_, wkvl + (size_t)768 * CT_, CT_, CI_);
    // 7: bias concat
    concat_bias<<<6, 256>>>(bk, bv, bkv);
    // 8: fused K|V projection
    gemm_mma<512, KVW, 0><<<dim3(12, KVROWS / 128), 256, GEMM_SMEM>>>(
        th, tl, wkvh, wkvl, bkv, kvs, nullptr, nullptr);
    // 9: attention + residual -> fused hi/lo
    attn_kernel<<<dim3(12, B_), 256>>>(qs, kvs, vis, fh, fl);
    // 10: transpose W1
    transpose_split<<<dim3(CI_ / 32, CI_ / 32), 256>>>(W1, w1h, w1l, CI_, CI_);
    // 11: MLP1 + gelu + fused W2 head -> partials
    gemm_mma<768, 768, 1><<<dim3(6, NROWS / 128), 256, GEMM_SMEM>>>(
        fh, fl, w1h, w1l, b1, nullptr, W2, partp);
    // 12: reduce partials + bias; fill rel
    reduce_head<<<(NROWS + 255) / 256, 256>>>(partp, b2, out);
}

// round 7
// speedup vs baseline: 1.4937x; 1.2573x over previous
#include <cuda_runtime.h>
#include <cuda_fp16.h>
#include <cstdint>

// Problem constants
#define B_   256
#define NV_  196
#define LT_  32
#define CI_  768
#define CT_  512
#define NROWS (B_*NV_)      // 50176
#define KVROWS (B_*LT_)     // 8192
#define KVW   1536          // fused K|V output width

// -------------------- scratch (device globals; no allocation) --------------------
__device__ __half g_vis_h [(size_t)NROWS * CI_];
__device__ __half g_text_h[(size_t)KVROWS * CT_];
__device__ __half g_wqT_hi [(size_t)CI_ * CI_];
__device__ __half g_wqT_lo [(size_t)CI_ * CI_];
__device__ __half g_wkvT_hi[(size_t)KVW * CT_];
__device__ __half g_wkvT_lo[(size_t)KVW * CT_];
__device__ __half g_w1T_hi [(size_t)CI_ * CI_];
__device__ __half g_w1T_lo [(size_t)CI_ * CI_];
__device__ __half g_fused_h[(size_t)NROWS * CI_];
__device__ float g_q  [(size_t)NROWS * CI_];
__device__ float g_kv [(size_t)KVROWS * KVW];
__device__ float g_bkv[KVW];
__device__ float g_part[(size_t)6 * NROWS * 2];

// -------------------- small helpers --------------------
__device__ __forceinline__ float qgelu(float x) {
    return x / (1.0f + __expf(-1.702f * x));
}
__device__ __forceinline__ void split_h(float x, __half& h, __half& l) {
    h = __float2half(x);
    l = __float2half(x - __half2float(h));
}
__device__ __forceinline__ uint32_t pack_h2(__half a, __half b) {
    uint32_t la = (uint32_t)__half_as_ushort(a);
    uint32_t lb = (uint32_t)__half_as_ushort(b);
    return la | (lb << 16);
}
__device__ __forceinline__ uint32_t smem_u32(const void* p) {
    uint32_t a;
    asm("{ .reg .u64 t; cvta.to.shared.u64 t, %1; cvt.u32.u64 %0, t; }" : "=r"(a) : "l"(p));
    return a;
}

// -------------------- mma / ldmatrix / cp.async primitives (base sm_103) --------
__device__ __forceinline__ void ldsm_x4(uint32_t* r, uint32_t addr) {
    asm volatile("ldmatrix.sync.aligned.m8n8.x4.shared.b16 {%0,%1,%2,%3}, [%4];"
                 : "=r"(r[0]), "=r"(r[1]), "=r"(r[2]), "=r"(r[3]) : "r"(addr));
}
__device__ __forceinline__ void mma_fp16(float* d, const uint32_t* a, const uint32_t* b) {
    asm volatile(
        "mma.sync.aligned.m16n8k16.row.col.f32.f16.f16.f32 "
        "{%0,%1,%2,%3}, {%4,%5,%6,%7}, {%8,%9}, {%0,%1,%2,%3};"
        : "+f"(d[0]), "+f"(d[1]), "+f"(d[2]), "+f"(d[3])
        : "r"(a[0]), "r"(a[1]), "r"(a[2]), "r"(a[3]), "r"(b[0]), "r"(b[1]));
}
__device__ __forceinline__ void cp_async16(uint32_t dst, const void* src) {
    asm volatile("cp.async.ca.shared.global [%0], [%1], 16;" :: "r"(dst), "l"(src));
}
__device__ __forceinline__ void cp_commit() {
    asm volatile("cp.async.commit_group;");
}
__device__ __forceinline__ void cp_wait1() {
    asm volatile("cp.async.wait_group 1;");
}

// -------------------- fp16x2 tensor-core GEMM --------------------
// C[M,OUTN] = Ah[M,K](fp16) @ (Bhi+Blo)[OUTN,K]^T + bias.
// Exact interpretation: D = Ah * B; only error = fp16 rounding of A (2^-12).
// Tile 128x128x32, 256 threads, 3-stage cp.async pipeline, 2 CTAs/SM.
#define SST 40
#define TILE_B (128 * SST * 2)          // 10240 B per tile
#define STAGE_B (3 * TILE_B)            // Ah, Bh, Bl = 30720 B
#define GEMM_SMEM (3 * STAGE_B)         // 92160 B -> 2 CTAs/SM

__device__ __forceinline__ void issue_tile(uint32_t dst, const __half* src,
                                           int ld, int tid) {
#pragma unroll
    for (int it = 0; it < 2; it++) {
        int id = tid + it * 256;
        int r = id >> 2, c = id & 3;
        cp_async16(dst + r * (SST * 2) + c * 16, src + (size_t)r * ld + c * 8);
    }
}

template<int KDIM, int OUTN, int DO_HEAD>
__global__ __launch_bounds__(256, 2)
void gemm_mma(const __half* __restrict__ Ah_g,
              const __half* __restrict__ Bhi, const __half* __restrict__ Blo,
              const float* __restrict__ bias, float* __restrict__ C,
              const float* __restrict__ W2p, float* __restrict__ part) {
    extern __shared__ char smem[];
    const int tid = threadIdx.x;
    const int lane = tid & 31;
    const int wid = tid >> 5;
    const int wm = wid & 3;
    const int wn = wid >> 2;
    const int n0 = blockIdx.x * 128;
    const int m0 = blockIdx.y * 128;

    const uint32_t sbase = smem_u32(smem);

    const __half* Ah = Ah_g + (size_t)m0 * KDIM;
    const __half* Bh = Bhi + (size_t)n0 * KDIM;
    const __half* Bl = Blo + (size_t)n0 * KDIM;

    constexpr int NC = KDIM / 32;

    float acc[2][8][4];
#pragma unroll
    for (int i = 0; i < 2; i++)
#pragma unroll
        for (int j = 0; j < 8; j++)
#pragma unroll
            for (int k = 0; k < 4; k++) acc[i][j][k] = 0.f;

    // prologue: chunks 0,1 -> stages 0,1
#pragma unroll
    for (int p = 0; p < 2; p++) {
        uint32_t st = sbase + p * STAGE_B;
        issue_tile(st,              Ah + p * 32, KDIM, tid);
        issue_tile(st + TILE_B,     Bh + p * 32, KDIM, tid);
        issue_tile(st + 2 * TILE_B, Bl + p * 32, KDIM, tid);
        cp_commit();
    }

    const int a_row = wm * 32 + (lane & 15);
    const int a_colb = ((lane >> 4) << 3) * 2;
    const int b_row = wn * 64 + (lane & 7) + ((lane >> 4) << 3);
    const int b_colb = (((lane >> 3) & 1) << 3) * 2;

    for (int c = 0; c < NC; c++) {
        cp_wait1();          // chunk c resident (<=1 group pending)
        __syncthreads();     // all warps done with iter c-1 before reusing its stage
        if (c + 2 < NC) {
            uint32_t st = sbase + ((c + 2) % 3) * STAGE_B;
            int k0 = (c + 2) * 32;
            issue_tile(st,              Ah + k0, KDIM, tid);
            issue_tile(st + TILE_B,     Bh + k0, KDIM, tid);
            issue_tile(st + 2 * TILE_B, Bl + k0, KDIM, tid);
        }
        cp_commit();

        uint32_t st = sbase + (c % 3) * STAGE_B;
#pragma unroll
        for (int ks = 0; ks < 2; ks++) {
            const int kb = ks * 32;
            uint32_t Af[2][4];
#pragma unroll
            for (int mi = 0; mi < 2; mi++) {
                uint32_t arow = (a_row + mi * 16) * (SST * 2) + kb + a_colb;
                ldsm_x4(Af[mi], st + arow);
            }
            uint32_t Bhf[4][4], Blf[4][4];
#pragma unroll
            for (int ni2 = 0; ni2 < 4; ni2++) {
                uint32_t brow = (b_row + ni2 * 16) * (SST * 2) + kb + b_colb;
                ldsm_x4(Bhf[ni2], st + TILE_B + brow);
                ldsm_x4(Blf[ni2], st + 2 * TILE_B + brow);
            }
#pragma unroll
            for (int mi = 0; mi < 2; mi++)
#pragma unroll
                for (int ni = 0; ni < 8; ni++) {
                    const int ni2 = ni >> 1, od = (ni & 1) * 2;
                    mma_fp16(acc[mi][ni], Af[mi], &Bhf[ni2][od]);
                    mma_fp16(acc[mi][ni], Af[mi], &Blf[ni2][od]);
                }
        }
    }

    if (!DO_HEAD) {
#pragma unroll
        for (int mi = 0; mi < 2; mi++) {
            int row0 = m0 + wm * 32 + mi * 16 + (lane >> 2);
#pragma unroll
            for (int ni = 0; ni < 8; ni++) {
                int col = n0 + wn * 64 + ni * 8 + (lane & 3) * 2;
                float b0 = bias[col], b1 = bias[col + 1];
                *(float2*)(C + (size_t)row0 * OUTN + col) =
                    make_float2(acc[mi][ni][0] + b0, acc[mi][ni][1] + b1);
                *(float2*)(C + (size_t)(row0 + 8) * OUTN + col) =
                    make_float2(acc[mi][ni][2] + b0, acc[mi][ni][3] + b1);
            }
        }
    } else {
        // fused head: p[row][2] = sum_cols qgelu(acc + b1[col]) * W2[col][:]
        __syncthreads();
        float* red = (float*)smem;
        const float2* w2 = (const float2*)W2p;
#pragma unroll
        for (int mi = 0; mi < 2; mi++) {
            float pa0 = 0.f, pa1 = 0.f, pb0 = 0.f, pb1 = 0.f;
#pragma unroll
            for (int ni = 0; ni < 8; ni++) {
                int col = n0 + wn * 64 + ni * 8 + (lane & 3) * 2;
                float b0 = bias[col], b1 = bias[col + 1];
                float v0 = qgelu(acc[mi][ni][0] + b0);
                float v1 = qgelu(acc[mi][ni][1] + b1);
                float v2 = qgelu(acc[mi][ni][2] + b0);
                float v3 = qgelu(acc[mi][ni][3] + b1);
                float2 wA = w2[col], wB = w2[col + 1];
                pa0 += v0 * wA.x + v1 * wB.x;
                pa1 += v0 * wA.y + v1 * wB.y;
                pb0 += v2 * wA.x + v3 * wB.x;
                pb1 += v2 * wA.y + v3 * wB.y;
            }
#pragma unroll
            for (int off = 1; off <= 2; off <<= 1) {
                pa0 += __shfl_xor_sync(0xffffffffu, pa0, off);
                pa1 += __shfl_xor_sync(0xffffffffu, pa1, off);
                pb0 += __shfl_xor_sync(0xffffffffu, pb0, off);
                pb1 += __shfl_xor_sync(0xffffffffu, pb1, off);
            }
            if ((lane & 3) == 0 && wn == 0) {
                int lrA = wm * 32 + mi * 16 + (lane >> 2);
                red[lrA * 2]           = pa0;
                red[lrA * 2 + 1]       = pa1;
                red[(lrA + 8) * 2]     = pb0;
                red[(lrA + 8) * 2 + 1] = pb1;
            }
        }
        __syncthreads();
#pragma unroll
        for (int mi = 0; mi < 2; mi++) {
            if (wn == 1) {
                float pa0 = 0.f, pa1 = 0.f, pb0 = 0.f, pb1 = 0.f;
#pragma unroll
                for (int ni = 0; ni < 8; ni++) {
                    int col = n0 + wn * 64 + ni * 8 + (lane & 3) * 2;
                    float b0 = bias[col], b1 = bias[col + 1];
                    float v0 = qgelu(acc[mi][ni][0] + b0);
                    float v1 = qgelu(acc[mi][ni][1] + b1);
                    float v2 = qgelu(acc[mi][ni][2] + b0);
                    float v3 = qgelu(acc[mi][ni][3] + b1);
                    float2 wA = w2[col], wB = w2[col + 1];
                    pa0 += v0 * wA.x + v1 * wB.x;
                    pa1 += v0 * wA.y + v1 * wB.y;
                    pb0 += v2 * wA.x + v3 * wB.x;
                    pb1 += v2 * wA.y + v3 * wB.y;
                }
#pragma unroll
                for (int off = 1; off <= 2; off <<= 1) {
                    pa0 += __shfl_xor_sync(0xffffffffu, pa0, off);
                    pa1 += __shfl_xor_sync(0xffffffffu, pa1, off);
                    pb0 += __shfl_xor_sync(0xffffffffu, pb0, off);
                    pb1 += __shfl_xor_sync(0xffffffffu, pb1, off);
                }
                if ((lane & 3) == 0) {
                    int lrA = wm * 32 + mi * 16 + (lane >> 2);
                    red[lrA * 2]           += pa0;
                    red[lrA * 2 + 1]       += pa1;
                    red[(lrA + 8) * 2]     += pb0;
                    red[(lrA + 8) * 2 + 1] += pb1;
                }
            }
        }
        __syncthreads();
        int row = tid >> 1, comp = tid & 1;
        part[((size_t)blockIdx.x * NROWS + m0 + row) * 2 + comp] = red[row * 2 + comp];
    }
}

// -------------------- fp32 -> fp16 convert --------------------
__global__ __launch_bounds__(256)
void cvt_kernel(const float* __restrict__ x, __half* __restrict__ h, int n4) {
    int i = blockIdx.x * blockDim.x + threadIdx.x;
    if (i >= n4) return;
    float4 v = ((const float4*)x)[i];
    ((uint2*)h)[i] = make_uint2(pack_h2(__float2half(v.x), __float2half(v.y)),
                                pack_h2(__float2half(v.z), __float2half(v.w)));
}

// -------------------- weight transpose + fp16 split: W[K,N] -> T[N,K] ----------
__global__ __launch_bounds__(256)
void transpose_split(const float* __restrict__ W, __half* __restrict__ Thi,
                     __half* __restrict__ Tlo, int K, int N) {
    __shared__ float t[32][33];
    int n0 = blockIdx.x * 32, k0 = blockIdx.y * 32;
    int tx = threadIdx.x & 31, ty = threadIdx.x >> 5;
#pragma unroll
    for (int s = 0; s < 4; s++)
        t[ty + 8 * s][tx] = W[(size_t)(k0 + ty + 8 * s) * N + n0 + tx];
    __syncthreads();
#pragma unroll
    for (int s = 0; s < 4; s++) {
        int n = n0 + ty + 8 * s;
        int k = k0 + tx;
        float v = t[tx][ty + 8 * s];
        __half h, l;
        split_h(v, h, l);
        Thi[(size_t)n * K + k] = h;
        Tlo[(size_t)n * K + k] = l;
    }
}

// -------------------- bias concat for fused KV --------------------
__global__ void concat_bias(const float* __restrict__ bk, const float* __restrict__ bv,
                            float* __restrict__ bkv) {
    int i = blockIdx.x * blockDim.x + threadIdx.x;
    if (i < 768) bkv[i] = bk[i];
    else if (i < 1536) bkv[i] = bv[i - 768];
}

// -------------------- attention; fused -> fp16 --------------------
__global__ __launch_bounds__(256)
void attn_kernel(const float* __restrict__ q_s, const float* __restrict__ kv,
                 const float* __restrict__ vis, __half* __restrict__ f_h) {
    int h = blockIdx.x;
    int b = blockIdx.y;
    __shared__ float4 ksm[32][16];
    __shared__ float4 vsm[32][16];
    int tid = threadIdx.x;

    const float* kbase = kv + (size_t)b * 32 * KVW + h * 64;
    const float* vbase = kbase + 768;
    for (int i = tid; i < 512; i += 256) {
        int l = i >> 4, d4 = i & 15;
        ksm[l][d4] = *(const float4*)(kbase + (size_t)l * KVW + d4 * 4);
        vsm[l][d4] = *(const float4*)(vbase + (size_t)l * KVW + d4 * 4);
    }
    __syncthreads();

    int n = tid;
    if (n >= 196) return;
    size_t rowoff = (size_t)(b * 196 + n) * 768 + h * 64;
    const float4* qrow = (const float4*)(q_s + rowoff);
    float4 q4[16];
#pragma unroll
    for (int d = 0; d < 16; d++) q4[d] = qrow[d];

    float s[32];
#pragma unroll
    for (int l = 0; l < 32; l++) {
        float ax = 0.f, ay = 0.f, az = 0.f, aw = 0.f;
#pragma unroll
        for (int d = 0; d < 16; d++) {
            float4 kk = ksm[l][d];
            ax += q4[d].x * kk.x;
            ay += q4[d].y * kk.y;
            az += q4[d].z * kk.z;
            aw += q4[d].w * kk.w;
        }
        s[l] = (ax + ay + az + aw) * 0.125f;
    }
    float m = s[0];
#pragma unroll
    for (int l = 1; l < 32; l++) m = fmaxf(m, s[l]);
    float sum = 0.f;
#pragma unroll
    for (int l = 0; l < 32; l++) { s[l] = __expf(s[l] - m); sum += s[l]; }
    float inv = 1.0f / sum;

    const float4* visrow = (const float4*)(vis + rowoff);
    uint2* hrow = (uint2*)(f_h + rowoff);
    for (int d = 0; d < 16; d++) {
        float ax = 0.f, ay = 0.f, az = 0.f, aw = 0.f;
#pragma unroll
        for (int l = 0; l < 32; l++) {
            float4 vv = vsm[l][d];
            float p = s[l];
            ax += p * vv.x;
            ay += p * vv.y;
            az += p * vv.z;
            aw += p * vv.w;
        }
        float4 r = visrow[d];
        hrow[d] = make_uint2(
            pack_h2(__float2half(ax * inv + r.x), __float2half(ay * inv + r.y)),
            pack_h2(__float2half(az * inv + r.z), __float2half(aw * inv + r.w)));
    }
}

// -------------------- head reduce: sum 6 partials + bias; fill rel -------------
__global__ __launch_bounds__(256)
void reduce_head(const float* __restrict__ part, const float* __restrict__ b2,
                 float* __restrict__ out) {
    int i = blockIdx.x * blockDim.x + threadIdx.x;
    if (i >= NROWS) return;
    float a0 = b2[0], a1 = b2[1];
#pragma unroll
    for (int p = 0; p < 6; p++) {
        a0 += part[((size_t)p * NROWS + i) * 2];
        a1 += part[((size_t)p * NROWS + i) * 2 + 1];
    }
    out[(size_t)i * 2]     = a0;
    out[(size_t)i * 2 + 1] = a1;
    out[(size_t)NROWS * 2 + i] = 1.0f / 32.0f;   // rel_BN == 1/Lt exactly
}

// -------------------- host launch --------------------
extern "C" void kernel_launch(void* const* d_in, const int* in_sizes, int n_in,
                              void* d_out, int out_size) {
    const float* vis  = (const float*)d_in[0];
    const float* text = (const float*)d_in[1];
    const float* Wq   = (const float*)d_in[2];
    const float* bq   = (const float*)d_in[3];
    const float* Wk   = (const float*)d_in[4];
    const float* bk   = (const float*)d_in[5];
    const float* Wv   = (const float*)d_in[6];
    const float* bv   = (const float*)d_in[7];
    const float* W1   = (const float*)d_in[8];
    const float* b1   = (const float*)d_in[9];
    const float* W2   = (const float*)d_in[10];
    const float* b2   = (const float*)d_in[11];
    float* out = (float*)d_out;

    __half *vh, *th, *wqh, *wql, *wkvh, *wkvl, *w1h, *w1l, *fh;
    float *qs, *kvs, *bkv, *partp;
    cudaGetSymbolAddress((void**)&vh,   g_vis_h);
    cudaGetSymbolAddress((void**)&th,   g_text_h);
    cudaGetSymbolAddress((void**)&wqh,  g_wqT_hi);
    cudaGetSymbolAddress((void**)&wql,  g_wqT_lo);
    cudaGetSymbolAddress((void**)&wkvh, g_wkvT_hi);
    cudaGetSymbolAddress((void**)&wkvl, g_wkvT_lo);
    cudaGetSymbolAddress((void**)&w1h,  g_w1T_hi);
    cudaGetSymbolAddress((void**)&w1l,  g_w1T_lo);
    cudaGetSymbolAddress((void**)&fh,   g_fused_h);
    cudaGetSymbolAddress((void**)&qs,   g_q);
    cudaGetSymbolAddress((void**)&kvs,  g_kv);
    cudaGetSymbolAddress((void**)&bkv,  g_bkv);
    cudaGetSymbolAddress((void**)&partp, g_part);

    cudaFuncSetAttribute(gemm_mma<768, 768, 0>, cudaFuncAttributeMaxDynamicSharedMemorySize, GEMM_SMEM);
    cudaFuncSetAttribute(gemm_mma<512, KVW, 0>, cudaFuncAttributeMaxDynamicSharedMemorySize, GEMM_SMEM);
    cudaFuncSetAttribute(gemm_mma<768, 768, 1>, cudaFuncAttributeMaxDynamicSharedMemorySize, GEMM_SMEM);

    // 1: convert vis -> fp16
    {
        int n4 = NROWS * CI_ / 4;
        cvt_kernel<<<(n4 + 255) / 256, 256>>>(vis, vh, n4);
    }
    // 2: convert text -> fp16
    {
        int n4 = KVROWS * CT_ / 4;
        cvt_kernel<<<(n4 + 255) / 256, 256>>>(text, th, n4);
    }
    // 3: transpose+split Wq
    transpose_split<<<dim3(CI_ / 32, CI_ / 32), 256>>>(Wq, wqh, wql, CI_, CI_);
    // 4: Q projection  <-- profiler slot
    gemm_mma<768, 768, 0><<<dim3(6, NROWS / 128), 256, GEMM_SMEM>>>(
        vh, wqh, wql, bq, qs, nullptr, nullptr);
    // 5-6: transpose Wk, Wv into fused wkv
    transpose_split<<<dim3(CI_ / 32, CT_ / 32), 256>>>(Wk, wkvh, wkvl, CT_, CI_);
    transpose_split<<<dim3(CI_ / 32, CT_ / 32), 256>>>(
        Wv, wkvh + (size_t)768 * CT_, wkvl + (size_t)768 * CT_, CT_, CI_);
    // 7: bias concat
    concat_bias<<<6, 256>>>(bk, bv, bkv);
    // 8: fused K|V projection
    gemm_mma<512, KVW, 0><<<dim3(12, KVROWS / 128), 256, GEMM_SMEM>>>(
        th, wkvh, wkvl, bkv, kvs, nullptr, nullptr);
    // 9: attention + residual -> fused fp16
    attn_kernel<<<dim3(12, B_), 256>>>(qs, kvs, vis, fh);
    // 10: transpose W1
    transpose_split<<<dim3(CI_ / 32, CI_ / 32), 256>>>(W1, w1h, w1l, CI_, CI_);
    // 11: MLP1 + gelu + fused W2 head -> partials
    gemm_mma<768, 768, 1><<<dim3(6, NROWS / 128), 256, GEMM_SMEM>>>(
        fh, w1h, w1l, b1, nullptr, W2, partp);
    // 12: reduce partials + bias; fill rel
    reduce_head<<<(NROWS + 255) / 256, 256>>>(partp, b2, out);
}

// round 9
// speedup vs baseline: 2.0097x; 1.3454x over previous
#include <cuda_runtime.h>
#include <cuda_fp16.h>
#include <cstdint>

// Problem constants
#define B_   256
#define NV_  196
#define LT_  32
#define CI_  768
#define CT_  512
#define NROWS (B_*NV_)      // 50176
#define KVROWS (B_*LT_)     // 8192
#define KVW   1536          // fused K|V output width

// -------------------- scratch (device globals; no allocation) --------------------
__device__ __half g_vis_h [(size_t)NROWS * CI_];
__device__ __half g_text_h[(size_t)KVROWS * CT_];
__device__ __half g_wqT  [(size_t)CI_ * CI_];
__device__ __half g_wkvT [(size_t)KVW * CT_];
__device__ __half g_w1T  [(size_t)CI_ * CI_];
__device__ __half g_fused_h[(size_t)NROWS * CI_];
__device__ __half g_qh [(size_t)NROWS * CI_];
__device__ float g_kv [(size_t)KVROWS * KVW];
__device__ float g_bkv[KVW];
__device__ float g_part[(size_t)6 * NROWS * 2];

// -------------------- small helpers --------------------
__device__ __forceinline__ float qgelu(float x) {
    return x / (1.0f + __expf(-1.702f * x));
}
__device__ __forceinline__ uint32_t pack_h2(__half a, __half b) {
    uint32_t la = (uint32_t)__half_as_ushort(a);
    uint32_t lb = (uint32_t)__half_as_ushort(b);
    return la | (lb << 16);
}
__device__ __forceinline__ uint32_t smem_u32(const void* p) {
    uint32_t a;
    asm("{ .reg .u64 t; cvta.to.shared.u64 t, %1; cvt.u32.u64 %0, t; }" : "=r"(a) : "l"(p));
    return a;
}

// -------------------- mma / ldmatrix / cp.async primitives (base sm_103) --------
__device__ __forceinline__ void ldsm_x4(uint32_t* r, uint32_t addr) {
    asm volatile("ldmatrix.sync.aligned.m8n8.x4.shared.b16 {%0,%1,%2,%3}, [%4];"
                 : "=r"(r[0]), "=r"(r[1]), "=r"(r[2]), "=r"(r[3]) : "r"(addr));
}
__device__ __forceinline__ void mma_fp16(float* d, const uint32_t* a, const uint32_t* b) {
    asm volatile(
        "mma.sync.aligned.m16n8k16.row.col.f32.f16.f16.f32 "
        "{%0,%1,%2,%3}, {%4,%5,%6,%7}, {%8,%9}, {%0,%1,%2,%3};"
        : "+f"(d[0]), "+f"(d[1]), "+f"(d[2]), "+f"(d[3])
        : "r"(a[0]), "r"(a[1]), "r"(a[2]), "r"(a[3]), "r"(b[0]), "r"(b[1]));
}
__device__ __forceinline__ void cp_async16(uint32_t dst, const void* src) {
    asm volatile("cp.async.ca.shared.global [%0], [%1], 16;" :: "r"(dst), "l"(src));
}
__device__ __forceinline__ void cp_commit() {
    asm volatile("cp.async.commit_group;");
}
__device__ __forceinline__ void cp_wait2() {
    asm volatile("cp.async.wait_group 2;");
}

// -------------------- fp16 tensor-core GEMM --------------------
// C[M,OUTN] = A[M,K](fp16) @ B[OUTN,K]^T(fp16) + bias.
// Tile 128x128x32, 256 threads, 4-stage cp.async pipeline, 2 CTAs/SM.
#define SST 40
#define TILE_B (128 * SST * 2)          // 10240 B per tile
#define STAGE_B (2 * TILE_B)            // A, B = 20480 B
#define NSTAGE 4
#define GEMM_SMEM (NSTAGE * STAGE_B)    // 81920 B -> 2 CTAs/SM

__device__ __forceinline__ void issue_tile(uint32_t dst, const __half* src,
                                           int ld, int tid) {
#pragma unroll
    for (int it = 0; it < 2; it++) {
        int id = tid + it * 256;
        int r = id >> 2, c = id & 3;
        cp_async16(dst + r * (SST * 2) + c * 16, src + (size_t)r * ld + c * 8);
    }
}

template<int KDIM, int OUTN, int DO_HEAD, int OUT_HALF>
__global__ __launch_bounds__(256, 2)
void gemm_mma(const __half* __restrict__ A_g, const __half* __restrict__ B_g,
              const float* __restrict__ bias, void* __restrict__ Cv,
              const float* __restrict__ W2p, float* __restrict__ part) {
    extern __shared__ char smem[];
    const int tid = threadIdx.x;
    const int lane = tid & 31;
    const int wid = tid >> 5;
    const int wm = wid & 3;
    const int wn = wid >> 2;
    const int n0 = blockIdx.x * 128;
    const int m0 = blockIdx.y * 128;

    const uint32_t sbase = smem_u32(smem);

    const __half* Ah = A_g + (size_t)m0 * KDIM;
    const __half* Bh = B_g + (size_t)n0 * KDIM;

    constexpr int NC = KDIM / 32;

    float acc[2][8][4];
#pragma unroll
    for (int i = 0; i < 2; i++)
#pragma unroll
        for (int j = 0; j < 8; j++)
#pragma unroll
            for (int k = 0; k < 4; k++) acc[i][j][k] = 0.f;

    // prologue: chunks 0..2 -> stages 0..2
#pragma unroll
    for (int p = 0; p < 3; p++) {
        uint32_t st = sbase + p * STAGE_B;
        issue_tile(st,          Ah + p * 32, KDIM, tid);
        issue_tile(st + TILE_B, Bh + p * 32, KDIM, tid);
        cp_commit();
    }

    const int a_row = wm * 32 + (lane & 15);
    const int a_colb = ((lane >> 4) << 3) * 2;
    const int b_row = wn * 64 + (lane & 7) + ((lane >> 4) << 3);
    const int b_colb = (((lane >> 3) & 1) << 3) * 2;

    for (int c = 0; c < NC; c++) {
        cp_wait2();          // chunk c resident (<=2 groups pending)
        __syncthreads();     // all warps done with iter c-1 before reusing its stage
        if (c + 3 < NC) {
            uint32_t st = sbase + ((c + 3) % NSTAGE) * STAGE_B;
            int k0 = (c + 3) * 32;
            issue_tile(st,          Ah + k0, KDIM, tid);
            issue_tile(st + TILE_B, Bh + k0, KDIM, tid);
        }
        cp_commit();

        uint32_t st = sbase + (c % NSTAGE) * STAGE_B;
#pragma unroll
        for (int ks = 0; ks < 2; ks++) {
            const int kb = ks * 32;
            uint32_t Af[2][4];
#pragma unroll
            for (int mi = 0; mi < 2; mi++) {
                uint32_t arow = (a_row + mi * 16) * (SST * 2) + kb + a_colb;
                ldsm_x4(Af[mi], st + arow);
            }
            uint32_t Bf[4][4];
#pragma unroll
            for (int ni2 = 0; ni2 < 4; ni2++) {
                uint32_t brow = (b_row + ni2 * 16) * (SST * 2) + kb + b_colb;
                ldsm_x4(Bf[ni2], st + TILE_B + brow);
            }
#pragma unroll
            for (int mi = 0; mi < 2; mi++)
#pragma unroll
                for (int ni = 0; ni < 8; ni++) {
                    const int ni2 = ni >> 1, od = (ni & 1) * 2;
                    mma_fp16(acc[mi][ni], Af[mi], &Bf[ni2][od]);
                }
        }
    }

    if (!DO_HEAD) {
#pragma unroll
        for (int mi = 0; mi < 2; mi++) {
            int row0 = m0 + wm * 32 + mi * 16 + (lane >> 2);
#pragma unroll
            for (int ni = 0; ni < 8; ni++) {
                int col = n0 + wn * 64 + ni * 8 + (lane & 3) * 2;
                float b0 = bias[col], b1 = bias[col + 1];
                float v0 = acc[mi][ni][0] + b0;
                float v1 = acc[mi][ni][1] + b1;
                float v2 = acc[mi][ni][2] + b0;
                float v3 = acc[mi][ni][3] + b1;
                if (OUT_HALF) {
                    __half* Ch = (__half*)Cv;
                    *(uint32_t*)(Ch + (size_t)row0 * OUTN + col) =
                        pack_h2(__float2half(v0), __float2half(v1));
                    *(uint32_t*)(Ch + (size_t)(row0 + 8) * OUTN + col) =
                        pack_h2(__float2half(v2), __float2half(v3));
                } else {
                    float* C = (float*)Cv;
                    *(float2*)(C + (size_t)row0 * OUTN + col)       = make_float2(v0, v1);
                    *(float2*)(C + (size_t)(row0 + 8) * OUTN + col) = make_float2(v2, v3);
                }
            }
        }
    } else {
        // fused head: p[row][2] = sum_cols qgelu(acc + b1[col]) * W2[col][:]
        __syncthreads();
        float* red = (float*)smem;
        const float2* w2 = (const float2*)W2p;
#pragma unroll
        for (int mi = 0; mi < 2; mi++) {
            float pa0 = 0.f, pa1 = 0.f, pb0 = 0.f, pb1 = 0.f;
#pragma unroll
            for (int ni = 0; ni < 8; ni++) {
                int col = n0 + wn * 64 + ni * 8 + (lane & 3) * 2;
                float b0 = bias[col], b1 = bias[col + 1];
                float v0 = qgelu(acc[mi][ni][0] + b0);
                float v1 = qgelu(acc[mi][ni][1] + b1);
                float v2 = qgelu(acc[mi][ni][2] + b0);
                float v3 = qgelu(acc[mi][ni][3] + b1);
                float2 wA = w2[col], wB = w2[col + 1];
                pa0 += v0 * wA.x + v1 * wB.x;
                pa1 += v0 * wA.y + v1 * wB.y;
                pb0 += v2 * wA.x + v3 * wB.x;
                pb1 += v2 * wA.y + v3 * wB.y;
            }
#pragma unroll
            for (int off = 1; off <= 2; off <<= 1) {
                pa0 += __shfl_xor_sync(0xffffffffu, pa0, off);
                pa1 += __shfl_xor_sync(0xffffffffu, pa1, off);
                pb0 += __shfl_xor_sync(0xffffffffu, pb0, off);
                pb1 += __shfl_xor_sync(0xffffffffu, pb1, off);
            }
            if ((lane & 3) == 0 && wn == 0) {
                int lrA = wm * 32 + mi * 16 + (lane >> 2);
                red[lrA * 2]           = pa0;
                red[lrA * 2 + 1]       = pa1;
                red[(lrA + 8) * 2]     = pb0;
                red[(lrA + 8) * 2 + 1] = pb1;
            }
        }
        __syncthreads();
#pragma unroll
        for (int mi = 0; mi < 2; mi++) {
            if (wn == 1) {
                float pa0 = 0.f, pa1 = 0.f, pb0 = 0.f, pb1 = 0.f;
#pragma unroll
                for (int ni = 0; ni < 8; ni++) {
                    int col = n0 + wn * 64 + ni * 8 + (lane & 3) * 2;
                    float b0 = bias[col], b1 = bias[col + 1];
                    float v0 = qgelu(acc[mi][ni][0] + b0);
                    float v1 = qgelu(acc[mi][ni][1] + b1);
                    float v2 = qgelu(acc[mi][ni][2] + b0);
                    float v3 = qgelu(acc[mi][ni][3] + b1);
                    float2 wA = w2[col], wB = w2[col + 1];
                    pa0 += v0 * wA.x + v1 * wB.x;
                    pa1 += v0 * wA.y + v1 * wB.y;
                    pb0 += v2 * wA.x + v3 * wB.x;
                    pb1 += v2 * wA.y + v3 * wB.y;
                }
#pragma unroll
                for (int off = 1; off <= 2; off <<= 1) {
                    pa0 += __shfl_xor_sync(0xffffffffu, pa0, off);
                    pa1 += __shfl_xor_sync(0xffffffffu, pa1, off);
                    pb0 += __shfl_xor_sync(0xffffffffu, pb0, off);
                    pb1 += __shfl_xor_sync(0xffffffffu, pb1, off);
                }
                if ((lane & 3) == 0) {
                    int lrA = wm * 32 + mi * 16 + (lane >> 2);
                    red[lrA * 2]           += pa0;
                    red[lrA * 2 + 1]       += pa1;
                    red[(lrA + 8) * 2]     += pb0;
                    red[(lrA + 8) * 2 + 1] += pb1;
                }
            }
        }
        __syncthreads();
        int row = tid >> 1, comp = tid & 1;
        part[((size_t)blockIdx.x * NROWS + m0 + row) * 2 + comp] = red[row * 2 + comp];
    }
}

// -------------------- fp32 -> fp16 convert --------------------
__global__ __launch_bounds__(256)
void cvt_kernel(const float* __restrict__ x, __half* __restrict__ h, int n4) {
    int i = blockIdx.x * blockDim.x + threadIdx.x;
    if (i >= n4) return;
    float4 v = ((const float4*)x)[i];
    ((uint2*)h)[i] = make_uint2(pack_h2(__float2half(v.x), __float2half(v.y)),
                                pack_h2(__float2half(v.z), __float2half(v.w)));
}

// -------------------- weight transpose -> fp16: W[K,N] -> T[N,K] ----------
__global__ __launch_bounds__(256)
void transpose_cvt(const float* __restrict__ W, __half* __restrict__ T, int K, int N) {
    __shared__ float t[32][33];
    int n0 = blockIdx.x * 32, k0 = blockIdx.y * 32;
    int tx = threadIdx.x & 31, ty = threadIdx.x >> 5;
#pragma unroll
    for (int s = 0; s < 4; s++)
        t[ty + 8 * s][tx] = W[(size_t)(k0 + ty + 8 * s) * N + n0 + tx];
    __syncthreads();
#pragma unroll
    for (int s = 0; s < 4; s++) {
        int n = n0 + ty + 8 * s;
        int k = k0 + tx;
        T[(size_t)n * K + k] = __float2half(t[tx][ty + 8 * s]);
    }
}

// -------------------- bias concat for fused KV --------------------
__global__ void concat_bias(const float* __restrict__ bk, const float* __restrict__ bv,
                            float* __restrict__ bkv) {
    int i = blockIdx.x * blockDim.x + threadIdx.x;
    if (i < 768) bkv[i] = bk[i];
    else if (i < 1536) bkv[i] = bv[i - 768];
}

// -------------------- attention; q fp16, kv fp32; fused -> fp16 ----------------
__global__ __launch_bounds__(256)
void attn_kernel(const __half* __restrict__ q_s, const float* __restrict__ kv,
                 const float* __restrict__ vis, __half* __restrict__ f_h) {
    int h = blockIdx.x;
    int b = blockIdx.y;
    __shared__ float4 ksm[32][16];
    __shared__ float4 vsm[32][16];
    int tid = threadIdx.x;

    const float* kbase = kv + (size_t)b * 32 * KVW + h * 64;
    const float* vbase = kbase + 768;
    for (int i = tid; i < 512; i += 256) {
        int l = i >> 4, d4 = i & 15;
        ksm[l][d4] = *(const float4*)(kbase + (size_t)l * KVW + d4 * 4);
        vsm[l][d4] = *(const float4*)(vbase + (size_t)l * KVW + d4 * 4);
    }
    __syncthreads();

    int n = tid;
    if (n >= 196) return;
    size_t rowoff = (size_t)(b * 196 + n) * 768 + h * 64;
    const uint2* qrow = (const uint2*)(q_s + rowoff);   // 16 x (4 halves)
    float4 q4[16];
#pragma unroll
    for (int d = 0; d < 16; d++) {
        uint2 u = qrow[d];
        float2 f0 = __half22float2(*(__half2*)&u.x);
        float2 f1 = __half22float2(*(__half2*)&u.y);
        q4[d] = make_float4(f0.x, f0.y, f1.x, f1.y);
    }

    float s[32];
#pragma unroll
    for (int l = 0; l < 32; l++) {
        float ax = 0.f, ay = 0.f, az = 0.f, aw = 0.f;
#pragma unroll
        for (int d = 0; d < 16; d++) {
            float4 kk = ksm[l][d];
            ax += q4[d].x * kk.x;
            ay += q4[d].y * kk.y;
            az += q4[d].z * kk.z;
            aw += q4[d].w * kk.w;
        }
        s[l] = (ax + ay + az + aw) * 0.125f;
    }
    float m = s[0];
#pragma unroll
    for (int l = 1; l < 32; l++) m = fmaxf(m, s[l]);
    float sum = 0.f;
#pragma unroll
    for (int l = 0; l < 32; l++) { s[l] = __expf(s[l] - m); sum += s[l]; }
    float inv = 1.0f / sum;

    const float4* visrow = (const float4*)(vis + rowoff);
    uint2* hrow = (uint2*)(f_h + rowoff);
    for (int d = 0; d < 16; d++) {
        float ax = 0.f, ay = 0.f, az = 0.f, aw = 0.f;
#pragma unroll
        for (int l = 0; l < 32; l++) {
            float4 vv = vsm[l][d];
            float p = s[l];
            ax += p * vv.x;
            ay += p * vv.y;
            az += p * vv.z;
            aw += p * vv.w;
        }
        float4 r = visrow[d];
        hrow[d] = make_uint2(
            pack_h2(__float2half(ax * inv + r.x), __float2half(ay * inv + r.y)),
            pack_h2(__float2half(az * inv + r.z), __float2half(aw * inv + r.w)));
    }
}

// -------------------- head reduce: sum 6 partials + bias; fill rel -------------
__global__ __launch_bounds__(256)
void reduce_head(const float* __restrict__ part, const float* __restrict__ b2,
                 float* __restrict__ out) {
    int i = blockIdx.x * blockDim.x + threadIdx.x;
    if (i >= NROWS) return;
    float a0 = b2[0], a1 = b2[1];
#pragma unroll
    for (int p = 0; p < 6; p++) {
        a0 += part[((size_t)p * NROWS + i) * 2];
        a1 += part[((size_t)p * NROWS + i) * 2 + 1];
    }
    out[(size_t)i * 2]     = a0;
    out[(size_t)i * 2 + 1] = a1;
    out[(size_t)NROWS * 2 + i] = 1.0f / 32.0f;   // rel_BN == 1/Lt exactly
}

// -------------------- host launch --------------------
extern "C" void kernel_launch(void* const* d_in, const int* in_sizes, int n_in,
                              void* d_out, int out_size) {
    const float* vis  = (const float*)d_in[0];
    const float* text = (const float*)d_in[1];
    const float* Wq   = (const float*)d_in[2];
    const float* bq   = (const float*)d_in[3];
    const float* Wk   = (const float*)d_in[4];
    const float* bk   = (const float*)d_in[5];
    const float* Wv   = (const float*)d_in[6];
    const float* bv   = (const float*)d_in[7];
    const float* W1   = (const float*)d_in[8];
    const float* b1   = (const float*)d_in[9];
    const float* W2   = (const float*)d_in[10];
    const float* b2   = (const float*)d_in[11];
    float* out = (float*)d_out;

    __half *vh, *th, *wq, *wkv, *w1, *fh, *qh;
    float *kvs, *bkv, *partp;
    cudaGetSymbolAddress((void**)&vh,   g_vis_h);
    cudaGetSymbolAddress((void**)&th,   g_text_h);
    cudaGetSymbolAddress((void**)&wq,   g_wqT);
    cudaGetSymbolAddress((void**)&wkv,  g_wkvT);
    cudaGetSymbolAddress((void**)&w1,   g_w1T);
    cudaGetSymbolAddress((void**)&fh,   g_fused_h);
    cudaGetSymbolAddress((void**)&qh,   g_qh);
    cudaGetSymbolAddress((void**)&kvs,  g_kv);
    cudaGetSymbolAddress((void**)&bkv,  g_bkv);
    cudaGetSymbolAddress((void**)&partp, g_part);

    cudaFuncSetAttribute(gemm_mma<768, 768, 0, 1>, cudaFuncAttributeMaxDynamicSharedMemorySize, GEMM_SMEM);
    cudaFuncSetAttribute(gemm_mma<512, KVW, 0, 0>, cudaFuncAttributeMaxDynamicSharedMemorySize, GEMM_SMEM);
    cudaFuncSetAttribute(gemm_mma<768, 768, 1, 0>, cudaFuncAttributeMaxDynamicSharedMemorySize, GEMM_SMEM);

    // 1: convert vis -> fp16
    {
        int n4 = NROWS * CI_ / 4;
        cvt_kernel<<<(n4 + 255) / 256, 256>>>(vis, vh, n4);
    }
    // 2: convert text -> fp16
    {
        int n4 = KVROWS * CT_ / 4;
        cvt_kernel<<<(n4 + 255) / 256, 256>>>(text, th, n4);
    }
    // 3: transpose Wq
    transpose_cvt<<<dim3(CI_ / 32, CI_ / 32), 256>>>(Wq, wq, CI_, CI_);
    // 4: Q projection (fp16 out)  <-- profiler slot
    gemm_mma<768, 768, 0, 1><<<dim3(6, NROWS / 128), 256, GEMM_SMEM>>>(
        vh, wq, bq, qh, nullptr, nullptr);
    // 5-6: transpose Wk, Wv into fused wkv
    transpose_cvt<<<dim3(CI_ / 32, CT_ / 32), 256>>>(Wk, wkv, CT_, CI_);
    transpose_cvt<<<dim3(CI_ / 32, CT_ / 32), 256>>>(Wv, wkv + (size_t)768 * CT_, CT_, CI_);
    // 7: bias concat
    concat_bias<<<6, 256>>>(bk, bv, bkv);
    // 8: fused K|V projection (fp32 out)
    gemm_mma<512, KVW, 0, 0><<<dim3(12, KVROWS / 128), 256, GEMM_SMEM>>>(
        th, wkv, bkv, kvs, nullptr, nullptr);
    // 9: attention + residual -> fused fp16
    attn_kernel<<<dim3(12, B_), 256>>>(qh, kvs, vis, fh);
    // 10: transpose W1
    transpose_cvt<<<dim3(CI_ / 32, CI_ / 32), 256>>>(W1, w1, CI_, CI_);
    // 11: MLP1 + gelu + fused W2 head -> partials
    gemm_mma<768, 768, 1, 0><<<dim3(6, NROWS / 128), 256, GEMM_SMEM>>>(
        fh, w1, b1, nullptr, W2, partp);
    // 12: reduce partials + bias; fill rel
    reduce_head<<<(NROWS + 255) / 256, 256>>>(partp, b2, out);
}

// round 11
// speedup vs baseline: 2.0245x; 1.0074x over previous
#include <cuda_runtime.h>
#include <cuda_fp16.h>
#include <cstdint>

// Problem constants
#define B_   256
#define NV_  196
#define LT_  32
#define CI_  768
#define CT_  512
#define NROWS (B_*NV_)      // 50176
#define KVROWS (B_*LT_)     // 8192
#define KVW   1536          // fused K|V output width

// -------------------- scratch (device globals; no allocation) --------------------
__device__ __half g_vis_h [(size_t)NROWS * CI_];
__device__ __half g_text_h[(size_t)KVROWS * CT_];
__device__ __half g_wqT  [(size_t)CI_ * CI_];
__device__ __half g_wkvT [(size_t)KVW * CT_];
__device__ __half g_w1T  [(size_t)CI_ * CI_];
__device__ __half g_fused_h[(size_t)NROWS * CI_];
__device__ __half g_qh [(size_t)NROWS * CI_];
__device__ __half g_kvh[(size_t)KVROWS * KVW];
__device__ float g_bkv[KVW];
__device__ float g_part[(size_t)6 * NROWS * 2];

// -------------------- small helpers --------------------
__device__ __forceinline__ float qgelu(float x) {
    return x / (1.0f + __expf(-1.702f * x));
}
__device__ __forceinline__ uint32_t pack_h2(__half a, __half b) {
    uint32_t la = (uint32_t)__half_as_ushort(a);
    uint32_t lb = (uint32_t)__half_as_ushort(b);
    return la | (lb << 16);
}
__device__ __forceinline__ uint32_t smem_u32(const void* p) {
    uint32_t a;
    asm("{ .reg .u64 t; cvta.to.shared.u64 t, %1; cvt.u32.u64 %0, t; }" : "=r"(a) : "l"(p));
    return a;
}

// -------------------- mma / ldmatrix / cp.async primitives (base sm_103) --------
__device__ __forceinline__ void ldsm_x4(uint32_t* r, uint32_t addr) {
    asm volatile("ldmatrix.sync.aligned.m8n8.x4.shared.b16 {%0,%1,%2,%3}, [%4];"
                 : "=r"(r[0]), "=r"(r[1]), "=r"(r[2]), "=r"(r[3]) : "r"(addr));
}
__device__ __forceinline__ void mma_fp16(float* d, const uint32_t* a, const uint32_t* b) {
    asm volatile(
        "mma.sync.aligned.m16n8k16.row.col.f32.f16.f16.f32 "
        "{%0,%1,%2,%3}, {%4,%5,%6,%7}, {%8,%9}, {%0,%1,%2,%3};"
        : "+f"(d[0]), "+f"(d[1]), "+f"(d[2]), "+f"(d[3])
        : "r"(a[0]), "r"(a[1]), "r"(a[2]), "r"(a[3]), "r"(b[0]), "r"(b[1]));
}
__device__ __forceinline__ void cp_async16(uint32_t dst, const void* src) {
    // .cg: bypass L1 on the fill path -> frees L1 crossbar for ldsm reads
    asm volatile("cp.async.cg.shared.global [%0], [%1], 16;" :: "r"(dst), "l"(src));
}
__device__ __forceinline__ void cp_commit() {
    asm volatile("cp.async.commit_group;");
}
__device__ __forceinline__ void cp_wait2() {
    asm volatile("cp.async.wait_group 2;");
}

// -------------------- fp16 tensor-core GEMM --------------------
// C[M,OUTN] = A[M,K](fp16) @ B[OUTN,K]^T(fp16) + bias.
// Tile 128x128x32, 256 threads, 4-stage cp.async pipeline, 2 CTAs/SM.
#define SST 40
#define TILE_B (128 * SST * 2)          // 10240 B per tile
#define STAGE_B (2 * TILE_B)            // A, B = 20480 B
#define NSTAGE 4
#define GEMM_SMEM (NSTAGE * STAGE_B)    // 81920 B -> 2 CTAs/SM

__device__ __forceinline__ void issue_tile(uint32_t dst, const __half* src,
                                           int ld, int tid) {
#pragma unroll
    for (int it = 0; it < 2; it++) {
        int id = tid + it * 256;
        int r = id >> 2, c = id & 3;
        cp_async16(dst + r * (SST * 2) + c * 16, src + (size_t)r * ld + c * 8);
    }
}

template<int KDIM, int OUTN, int DO_HEAD, int OUT_HALF>
__global__ __launch_bounds__(256, 2)
void gemm_mma(const __half* __restrict__ A_g, const __half* __restrict__ B_g,
              const float* __restrict__ bias, void* __restrict__ Cv,
              const float* __restrict__ W2p, float* __restrict__ part) {
    extern __shared__ char smem[];
    const int tid = threadIdx.x;
    const int lane = tid & 31;
    const int wid = tid >> 5;
    const int wm = wid & 3;
    const int wn = wid >> 2;
    const int n0 = blockIdx.x * 128;
    const int m0 = blockIdx.y * 128;

    const uint32_t sbase = smem_u32(smem);

    const __half* Ah = A_g + (size_t)m0 * KDIM;
    const __half* Bh = B_g + (size_t)n0 * KDIM;

    constexpr int NC = KDIM / 32;

    float acc[2][8][4];
#pragma unroll
    for (int i = 0; i < 2; i++)
#pragma unroll
        for (int j = 0; j < 8; j++)
#pragma unroll
            for (int k = 0; k < 4; k++) acc[i][j][k] = 0.f;

    // prologue: chunks 0..2 -> stages 0..2
#pragma unroll
    for (int p = 0; p < 3; p++) {
        uint32_t st = sbase + p * STAGE_B;
        issue_tile(st,          Ah + p * 32, KDIM, tid);
        issue_tile(st + TILE_B, Bh + p * 32, KDIM, tid);
        cp_commit();
    }

    const int a_row = wm * 32 + (lane & 15);
    const int a_colb = ((lane >> 4) << 3) * 2;
    const int b_row = wn * 64 + (lane & 7) + ((lane >> 4) << 3);
    const int b_colb = (((lane >> 3) & 1) << 3) * 2;

    for (int c = 0; c < NC; c++) {
        cp_wait2();          // chunk c resident (<=2 groups pending)
        __syncthreads();     // all warps done with iter c-1 before reusing its stage
        if (c + 3 < NC) {
            uint32_t st = sbase + ((c + 3) % NSTAGE) * STAGE_B;
            int k0 = (c + 3) * 32;
            issue_tile(st,          Ah + k0, KDIM, tid);
            issue_tile(st + TILE_B, Bh + k0, KDIM, tid);
        }
        cp_commit();

        uint32_t st = sbase + (c % NSTAGE) * STAGE_B;
#pragma unroll
        for (int ks = 0; ks < 2; ks++) {
            const int kb = ks * 32;
            uint32_t Af[2][4];
#pragma unroll
            for (int mi = 0; mi < 2; mi++) {
                uint32_t arow = (a_row + mi * 16) * (SST * 2) + kb + a_colb;
                ldsm_x4(Af[mi], st + arow);
            }
            uint32_t Bf[4][4];
#pragma unroll
            for (int ni2 = 0; ni2 < 4; ni2++) {
                uint32_t brow = (b_row + ni2 * 16) * (SST * 2) + kb + b_colb;
                ldsm_x4(Bf[ni2], st + TILE_B + brow);
            }
#pragma unroll
            for (int mi = 0; mi < 2; mi++)
#pragma unroll
                for (int ni = 0; ni < 8; ni++) {
                    const int ni2 = ni >> 1, od = (ni & 1) * 2;
                    mma_fp16(acc[mi][ni], Af[mi], &Bf[ni2][od]);
                }
        }
    }

    if (!DO_HEAD) {
#pragma unroll
        for (int mi = 0; mi < 2; mi++) {
            int row0 = m0 + wm * 32 + mi * 16 + (lane >> 2);
#pragma unroll
            for (int ni = 0; ni < 8; ni++) {
                int col = n0 + wn * 64 + ni * 8 + (lane & 3) * 2;
                float b0 = bias[col], b1 = bias[col + 1];
                float v0 = acc[mi][ni][0] + b0;
                float v1 = acc[mi][ni][1] + b1;
                float v2 = acc[mi][ni][2] + b0;
                float v3 = acc[mi][ni][3] + b1;
                if (OUT_HALF) {
                    __half* Ch = (__half*)Cv;
                    *(uint32_t*)(Ch + (size_t)row0 * OUTN + col) =
                        pack_h2(__float2half(v0), __float2half(v1));
                    *(uint32_t*)(Ch + (size_t)(row0 + 8) * OUTN + col) =
                        pack_h2(__float2half(v2), __float2half(v3));
                } else {
                    float* C = (float*)Cv;
                    *(float2*)(C + (size_t)row0 * OUTN + col)       = make_float2(v0, v1);
                    *(float2*)(C + (size_t)(row0 + 8) * OUTN + col) = make_float2(v2, v3);
                }
            }
        }
    } else {
        // fused head: p[row][2] = sum_cols qgelu(acc + b1[col]) * W2[col][:]
        __syncthreads();
        float* red = (float*)smem;
        const float2* w2 = (const float2*)W2p;
#pragma unroll
        for (int mi = 0; mi < 2; mi++) {
            float pa0 = 0.f, pa1 = 0.f, pb0 = 0.f, pb1 = 0.f;
#pragma unroll
            for (int ni = 0; ni < 8; ni++) {
                int col = n0 + wn * 64 + ni * 8 + (lane & 3) * 2;
                float b0 = bias[col], b1 = bias[col + 1];
                float v0 = qgelu(acc[mi][ni][0] + b0);
                float v1 = qgelu(acc[mi][ni][1] + b1);
                float v2 = qgelu(acc[mi][ni][2] + b0);
                float v3 = qgelu(acc[mi][ni][3] + b1);
                float2 wA = w2[col], wB = w2[col + 1];
                pa0 += v0 * wA.x + v1 * wB.x;
                pa1 += v0 * wA.y + v1 * wB.y;
                pb0 += v2 * wA.x + v3 * wB.x;
                pb1 += v2 * wA.y + v3 * wB.y;
            }
#pragma unroll
            for (int off = 1; off <= 2; off <<= 1) {
                pa0 += __shfl_xor_sync(0xffffffffu, pa0, off);
                pa1 += __shfl_xor_sync(0xffffffffu, pa1, off);
                pb0 += __shfl_xor_sync(0xffffffffu, pb0, off);
                pb1 += __shfl_xor_sync(0xffffffffu, pb1, off);
            }
            if ((lane & 3) == 0 && wn == 0) {
                int lrA = wm * 32 + mi * 16 + (lane >> 2);
                red[lrA * 2]           = pa0;
                red[lrA * 2 + 1]       = pa1;
                red[(lrA + 8) * 2]     = pb0;
                red[(lrA + 8) * 2 + 1] = pb1;
            }
        }
        __syncthreads();
#pragma unroll
        for (int mi = 0; mi < 2; mi++) {
            if (wn == 1) {
                float pa0 = 0.f, pa1 = 0.f, pb0 = 0.f, pb1 = 0.f;
#pragma unroll
                for (int ni = 0; ni < 8; ni++) {
                    int col = n0 + wn * 64 + ni * 8 + (lane & 3) * 2;
                    float b0 = bias[col], b1 = bias[col + 1];
                    float v0 = qgelu(acc[mi][ni][0] + b0);
                    float v1 = qgelu(acc[mi][ni][1] + b1);
                    float v2 = qgelu(acc[mi][ni][2] + b0);
                    float v3 = qgelu(acc[mi][ni][3] + b1);
                    float2 wA = w2[col], wB = w2[col + 1];
                    pa0 += v0 * wA.x + v1 * wB.x;
                    pa1 += v0 * wA.y + v1 * wB.y;
                    pb0 += v2 * wA.x + v3 * wB.x;
                    pb1 += v2 * wA.y + v3 * wB.y;
                }
#pragma unroll
                for (int off = 1; off <= 2; off <<= 1) {
                    pa0 += __shfl_xor_sync(0xffffffffu, pa0, off);
                    pa1 += __shfl_xor_sync(0xffffffffu, pa1, off);
                    pb0 += __shfl_xor_sync(0xffffffffu, pb0, off);
                    pb1 += __shfl_xor_sync(0xffffffffu, pb1, off);
                }
                if ((lane & 3) == 0) {
                    int lrA = wm * 32 + mi * 16 + (lane >> 2);
                    red[lrA * 2]           += pa0;
                    red[lrA * 2 + 1]       += pa1;
                    red[(lrA + 8) * 2]     += pb0;
                    red[(lrA + 8) * 2 + 1] += pb1;
                }
            }
        }
        __syncthreads();
        int row = tid >> 1, comp = tid & 1;
        part[((size_t)blockIdx.x * NROWS + m0 + row) * 2 + comp] = red[row * 2 + comp];
    }
}

// -------------------- fp32 -> fp16 convert --------------------
__global__ __launch_bounds__(256)
void cvt_kernel(const float* __restrict__ x, __half* __restrict__ h, int n4) {
    int i = blockIdx.x * blockDim.x + threadIdx.x;
    if (i >= n4) return;
    float4 v = ((const float4*)x)[i];
    ((uint2*)h)[i] = make_uint2(pack_h2(__float2half(v.x), __float2half(v.y)),
                                pack_h2(__float2half(v.z), __float2half(v.w)));
}

// -------------------- weight transpose -> fp16: W[K,N] -> T[N,K] ----------
__global__ __launch_bounds__(256)
void transpose_cvt(const float* __restrict__ W, __half* __restrict__ T, int K, int N) {
    __shared__ float t[32][33];
    int n0 = blockIdx.x * 32, k0 = blockIdx.y * 32;
    int tx = threadIdx.x & 31, ty = threadIdx.x >> 5;
#pragma unroll
    for (int s = 0; s < 4; s++)
        t[ty + 8 * s][tx] = W[(size_t)(k0 + ty + 8 * s) * N + n0 + tx];
    __syncthreads();
#pragma unroll
    for (int s = 0; s < 4; s++) {
        int n = n0 + ty + 8 * s;
        int k = k0 + tx;
        T[(size_t)n * K + k] = __float2half(t[tx][ty + 8 * s]);
    }
}

// -------------------- bias concat for fused KV --------------------
__global__ void concat_bias(const float* __restrict__ bk, const float* __restrict__ bv,
                            float* __restrict__ bkv) {
    int i = blockIdx.x * blockDim.x + threadIdx.x;
    if (i < 768) bkv[i] = bk[i];
    else if (i < 1536) bkv[i] = bv[i - 768];
}

// -------------------- attention; q fp16, kv fp16 in smem; fused -> fp16 --------
__global__ __launch_bounds__(256)
void attn_kernel(const __half* __restrict__ q_s, const __half* __restrict__ kv,
                 const float* __restrict__ vis, __half* __restrict__ f_h) {
    int h = blockIdx.x;
    int b = blockIdx.y;
    __shared__ uint4 ksm[32][8];   // 32 rows x 64 halves
    __shared__ uint4 vsm[32][8];
    int tid = threadIdx.x;

    const __half* kbase = kv + (size_t)b * 32 * KVW + h * 64;
    const __half* vbase = kbase + 768;
    for (int i = tid; i < 256; i += 256) {
        int l = i >> 3, u = i & 7;
        ksm[l][u] = *(const uint4*)(kbase + (size_t)l * KVW + u * 8);
        vsm[l][u] = *(const uint4*)(vbase + (size_t)l * KVW + u * 8);
    }
    __syncthreads();

    int n = tid;
    if (n >= 196) return;
    size_t rowoff = (size_t)(b * 196 + n) * 768 + h * 64;
    const uint2* qrow = (const uint2*)(q_s + rowoff);   // 16 x (4 halves)
    float4 q4[16];
#pragma unroll
    for (int d = 0; d < 16; d++) {
        uint2 u = qrow[d];
        float2 f0 = __half22float2(*(__half2*)&u.x);
        float2 f1 = __half22float2(*(__half2*)&u.y);
        q4[d] = make_float4(f0.x, f0.y, f1.x, f1.y);
    }

    float s[32];
#pragma unroll
    for (int l = 0; l < 32; l++) {
        float acc = 0.f;
#pragma unroll
        for (int u = 0; u < 8; u++) {
            uint4 kk = ksm[l][u];
            float2 k0 = __half22float2(*(__half2*)&kk.x);
            float2 k1 = __half22float2(*(__half2*)&kk.y);
            float2 k2 = __half22float2(*(__half2*)&kk.z);
            float2 k3 = __half22float2(*(__half2*)&kk.w);
            float4 qa = q4[u * 2], qb = q4[u * 2 + 1];
            acc += qa.x * k0.x + qa.y * k0.y + qa.z * k1.x + qa.w * k1.y
                 + qb.x * k2.x + qb.y * k2.y + qb.z * k3.x + qb.w * k3.y;
        }
        s[l] = acc * 0.125f;
    }
    float m = s[0];
#pragma unroll
    for (int l = 1; l < 32; l++) m = fmaxf(m, s[l]);
    float sum = 0.f;
#pragma unroll
    for (int l = 0; l < 32; l++) { s[l] = __expf(s[l] - m); sum += s[l]; }
    float inv = 1.0f / sum;
#pragma unroll
    for (int l = 0; l < 32; l++) s[l] *= inv;

    const float4* visrow = (const float4*)(vis + rowoff);
    uint2* hrow = (uint2*)(f_h + rowoff);
    for (int u = 0; u < 8; u++) {
        float a0 = 0.f, a1 = 0.f, a2 = 0.f, a3 = 0.f, a4 = 0.f, a5 = 0.f, a6 = 0.f, a7 = 0.f;
#pragma unroll
        for (int l = 0; l < 32; l++) {
            uint4 vv = vsm[l][u];
            float2 v0 = __half22float2(*(__half2*)&vv.x);
            float2 v1 = __half22float2(*(__half2*)&vv.y);
            float2 v2 = __half22float2(*(__half2*)&vv.z);
            float2 v3 = __half22float2(*(__half2*)&vv.w);
            float p = s[l];
            a0 += p * v0.x; a1 += p * v0.y; a2 += p * v1.x; a3 += p * v1.y;
            a4 += p * v2.x; a5 += p * v2.y; a6 += p * v3.x; a7 += p * v3.y;
        }
        float4 r0 = visrow[u * 2], r1 = visrow[u * 2 + 1];
        hrow[u * 2] = make_uint2(
            pack_h2(__float2half(a0 + r0.x), __float2half(a1 + r0.y)),
            pack_h2(__float2half(a2 + r0.z), __float2half(a3 + r0.w)));
        hrow[u * 2 + 1] = make_uint2(
            pack_h2(__float2half(a4 + r1.x), __float2half(a5 + r1.y)),
            pack_h2(__float2half(a6 + r1.z), __float2half(a7 + r1.w)));
    }
}

// -------------------- head reduce: sum 6 partials + bias; fill rel -------------
__global__ __launch_bounds__(256)
void reduce_head(const float* __restrict__ part, const float* __restrict__ b2,
                 float* __restrict__ out) {
    int i = blockIdx.x * blockDim.x + threadIdx.x;
    if (i >= NROWS) return;
    float a0 = b2[0], a1 = b2[1];
#pragma unroll
    for (int p = 0; p < 6; p++) {
        a0 += part[((size_t)p * NROWS + i) * 2];
        a1 += part[((size_t)p * NROWS + i) * 2 + 1];
    }
    out[(size_t)i * 2]     = a0;
    out[(size_t)i * 2 + 1] = a1;
    out[(size_t)NROWS * 2 + i] = 1.0f / 32.0f;   // rel_BN == 1/Lt exactly
}

// -------------------- host launch --------------------
extern "C" void kernel_launch(void* const* d_in, const int* in_sizes, int n_in,
                              void* d_out, int out_size) {
    const float* vis  = (const float*)d_in[0];
    const float* text = (const float*)d_in[1];
    const float* Wq   = (const float*)d_in[2];
    const float* bq   = (const float*)d_in[3];
    const float* Wk   = (const float*)d_in[4];
    const float* bk   = (const float*)d_in[5];
    const float* Wv   = (const float*)d_in[6];
    const float* bv   = (const float*)d_in[7];
    const float* W1   = (const float*)d_in[8];
    const float* b1   = (const float*)d_in[9];
    const float* W2   = (const float*)d_in[10];
    const float* b2   = (const float*)d_in[11];
    float* out = (float*)d_out;

    __half *vh, *th, *wq, *wkv, *w1, *fh, *qh, *kvh;
    float *bkv, *partp;
    cudaGetSymbolAddress((void**)&vh,   g_vis_h);
    cudaGetSymbolAddress((void**)&th,   g_text_h);
    cudaGetSymbolAddress((void**)&wq,   g_wqT);
    cudaGetSymbolAddress((void**)&wkv,  g_wkvT);
    cudaGetSymbolAddress((void**)&w1,   g_w1T);
    cudaGetSymbolAddress((void**)&fh,   g_fused_h);
    cudaGetSymbolAddress((void**)&qh,   g_qh);
    cudaGetSymbolAddress((void**)&kvh,  g_kvh);
    cudaGetSymbolAddress((void**)&bkv,  g_bkv);
    cudaGetSymbolAddress((void**)&partp, g_part);

    cudaFuncSetAttribute(gemm_mma<768, 768, 0, 1>, cudaFuncAttributeMaxDynamicSharedMemorySize, GEMM_SMEM);
    cudaFuncSetAttribute(gemm_mma<512, KVW, 0, 1>, cudaFuncAttributeMaxDynamicSharedMemorySize, GEMM_SMEM);
    cudaFuncSetAttribute(gemm_mma<768, 768, 1, 0>, cudaFuncAttributeMaxDynamicSharedMemorySize, GEMM_SMEM);

    // 1: convert vis -> fp16
    {
        int n4 = NROWS * CI_ / 4;
        cvt_kernel<<<(n4 + 255) / 256, 256>>>(vis, vh, n4);
    }
    // 2: convert text -> fp16
    {
        int n4 = KVROWS * CT_ / 4;
        cvt_kernel<<<(n4 + 255) / 256, 256>>>(text, th, n4);
    }
    // 3: transpose Wq
    transpose_cvt<<<dim3(CI_ / 32, CI_ / 32), 256>>>(Wq, wq, CI_, CI_);
    // 4: Q projection (fp16 out)  <-- profiler slot
    gemm_mma<768, 768, 0, 1><<<dim3(6, NROWS / 128), 256, GEMM_SMEM>>>(
        vh, wq, bq, qh, nullptr, nullptr);
    // 5-6: transpose Wk, Wv into fused wkv
    transpose_cvt<<<dim3(CI_ / 32, CT_ / 32), 256>>>(Wk, wkv, CT_, CI_);
    transpose_cvt<<<dim3(CI_ / 32, CT_ / 32), 256>>>(Wv, wkv + (size_t)768 * CT_, CT_, CI_);
    // 7: bias concat
    concat_bias<<<6, 256>>>(bk, bv, bkv);
    // 8: fused K|V projection (fp16 out)
    gemm_mma<512, KVW, 0, 1><<<dim3(12, KVROWS / 128), 256, GEMM_SMEM>>>(
        th, wkv, bkv, kvh, nullptr, nullptr);
    // 9: attention + residual -> fused fp16
    attn_kernel<<<dim3(12, B_), 256>>>(qh, kvh, vis, fh);
    // 10: transpose W1
    transpose_cvt<<<dim3(CI_ / 32, CI_ / 32), 256>>>(W1, w1, CI_, CI_);
    // 11: MLP1 + gelu + fused W2 head -> partials
    gemm_mma<768, 768, 1, 0><<<dim3(6, NROWS / 128), 256, GEMM_SMEM>>>(
        fh, w1, b1, nullptr, W2, partp);
    // 12: reduce partials + bias; fill rel
    reduce_head<<<(NROWS + 255) / 256, 256>>>(partp, b2, out);
}